// round 11
// baseline (speedup 1.0000x reference)
#include <cuda_runtime.h>
#include <cuda_fp16.h>
#include <math.h>
#include <cstdint>

#define S_  256
#define I_  512
#define CM  64
#define CZ  128
#define H_  8
#define CH  32
#define HC  256
#define NN  (S_*CH)   // 8192
#define EPS 1e-5f

// ---- scratch ----
__device__ __half d_mh[(size_t)S_*I_*CM];     // LN(m) fp16
__device__ __half d_vh[(size_t)H_*NN*I_];     // v fp16 [h][n][j], n = s*32+c
__device__ __half d_gh[(size_t)S_*I_*HC];     // sigmoid(g) fp16 [s*i][hc]
__device__ __half d_wh[(size_t)H_*I_*I_];     // softmax(w) fp16 [h][i][j]
__device__ __half d_oh[(size_t)H_*I_*NN];     // o fp16 [h][i][n]

__device__ __forceinline__ float warp_sum(float v) {
#pragma unroll
    for (int o = 16; o; o >>= 1) v += __shfl_xor_sync(0xffffffffu, v, o);
    return v;
}
__device__ __forceinline__ float warp_max(float v) {
#pragma unroll
    for (int o = 16; o; o >>= 1) v = fmaxf(v, __shfl_xor_sync(0xffffffffu, v, o));
    return v;
}
__device__ __forceinline__ uint32_t smem_u32(const void* p) {
    uint32_t a;
    asm("{ .reg .u64 t; cvta.to.shared.u64 t, %1; cvt.u32.u64 %0, t; }" : "=r"(a) : "l"(p));
    return a;
}
__device__ __forceinline__ void ldsm_x4(uint32_t& r0, uint32_t& r1, uint32_t& r2,
                                        uint32_t& r3, uint32_t addr) {
    asm volatile("ldmatrix.sync.aligned.m8n8.x4.shared.b16 {%0,%1,%2,%3}, [%4];"
                 : "=r"(r0), "=r"(r1), "=r"(r2), "=r"(r3) : "r"(addr));
}
__device__ __forceinline__ void cpa16(uint32_t dst, const void* src) {
    asm volatile("cp.async.cg.shared.global [%0], [%1], 16;" :: "r"(dst), "l"(src));
}
#define CP_COMMIT() asm volatile("cp.async.commit_group;" ::: "memory")

#define MMA_F16(d0,d1,d2,d3,a0,a1,a2,a3,b0,b1) \
    asm volatile("mma.sync.aligned.m16n8k16.row.col.f32.f16.f16.f32 " \
                 "{%0,%1,%2,%3},{%4,%5,%6,%7},{%8,%9},{%0,%1,%2,%3};" \
                 : "+f"(d0),"+f"(d1),"+f"(d2),"+f"(d3) \
                 : "r"(a0),"r"(a1),"r"(a2),"r"(a3),"r"(b0),"r"(b1))

// ---------------- K1: LayerNorm(m) -> fp16 ----------------
__global__ void k_ln_m(const float* __restrict__ m, const float* __restrict__ g,
                       const float* __restrict__ b) {
    int row  = blockIdx.x * 8 + (threadIdx.x >> 5);
    int lane = threadIdx.x & 31;
    const float2 v = *(const float2*)(m + (size_t)row * CM + lane * 2);
    float s  = warp_sum(v.x + v.y);
    float mu = s * (1.f / 64.f);
    float d0 = v.x - mu, d1 = v.y - mu;
    float var = warp_sum(d0 * d0 + d1 * d1) * (1.f / 64.f);
    float rs = rsqrtf(var + EPS);
    float2 gg = *(const float2*)(g + lane * 2);
    float2 bb = *(const float2*)(b + lane * 2);
    __half2 o = __floats2half2_rn(d0 * rs * gg.x + bb.x, d1 * rs * gg.y + bb.y);
    *(__half2*)(d_mh + (size_t)row * CM + lane * 2) = o;
}

// ---- K2: fused b-projection + softmax. Block per i; writes w fp16. ----
__global__ void __launch_bounds__(256) k_bsm(const float* __restrict__ z,
                                             const float* __restrict__ zg,
                                             const float* __restrict__ zb,
                                             const float* __restrict__ Wb,
                                             const float* __restrict__ zmask) {
    __shared__ __align__(16) float Wbs[H_ * CZ];
    __shared__ __align__(16) float zgs[CZ], zbs[CZ];
    __shared__ __align__(16) float bs[8][516];
    int t = threadIdx.x;
    int lane = t & 31, wid = t >> 5;
    int grp = t >> 3, sub = t & 7;
    int i = blockIdx.x;
    for (int idx = t; idx < H_ * CZ; idx += 256) Wbs[idx] = Wb[idx];
    if (t < CZ) { zgs[t] = zg[t]; zbs[t] = zb[t]; }
    __syncthreads();

#pragma unroll 1
    for (int p = 0; p < 16; p++) {
        int j = p * 32 + grp;
        const float* zp = z + ((size_t)i * I_ + j) * CZ + sub * 16;
        float4 v[4];
#pragma unroll
        for (int q = 0; q < 4; q++) v[q] = *(const float4*)(zp + q * 4);
        float s = 0.f, ss = 0.f;
#pragma unroll
        for (int q = 0; q < 4; q++) {
            s  += v[q].x + v[q].y + v[q].z + v[q].w;
            ss += v[q].x * v[q].x + v[q].y * v[q].y + v[q].z * v[q].z + v[q].w * v[q].w;
        }
#pragma unroll
        for (int o = 4; o; o >>= 1) {
            s  += __shfl_xor_sync(0xffffffffu, s, o);
            ss += __shfl_xor_sync(0xffffffffu, ss, o);
        }
        float mu = s * (1.f / 128.f);
        float var = ss * (1.f / 128.f) - mu * mu;
        float rs = rsqrtf(var + EPS);

        float xn[16];
#pragma unroll
        for (int q = 0; q < 4; q++) {
            float4 g4 = *(const float4*)(zgs + sub * 16 + q * 4);
            float4 b4 = *(const float4*)(zbs + sub * 16 + q * 4);
            xn[q * 4 + 0] = (v[q].x - mu) * rs * g4.x + b4.x;
            xn[q * 4 + 1] = (v[q].y - mu) * rs * g4.y + b4.y;
            xn[q * 4 + 2] = (v[q].z - mu) * rs * g4.z + b4.z;
            xn[q * 4 + 3] = (v[q].w - mu) * rs * g4.w + b4.w;
        }
        float pv[8];
#pragma unroll
        for (int h = 0; h < 8; h++) {
            float a = 0.f;
#pragma unroll
            for (int q = 0; q < 4; q++) {
                float4 w4 = *(const float4*)(Wbs + h * CZ + sub * 16 + q * 4);
                a += xn[q * 4 + 0] * w4.x + xn[q * 4 + 1] * w4.y +
                     xn[q * 4 + 2] * w4.z + xn[q * 4 + 3] * w4.w;
            }
            pv[h] = a;
        }
        bool b4_ = sub & 4, b2_ = sub & 2, b1_ = sub & 1;
        float q4[4];
#pragma unroll
        for (int h = 0; h < 4; h++) {
            float send = b4_ ? pv[h] : pv[h + 4];
            float recv = __shfl_xor_sync(0xffffffffu, send, 4);
            q4[h] = (b4_ ? pv[h + 4] : pv[h]) + recv;
        }
        float r2[2];
#pragma unroll
        for (int h = 0; h < 2; h++) {
            float send = b2_ ? q4[h] : q4[h + 2];
            float recv = __shfl_xor_sync(0xffffffffu, send, 2);
            r2[h] = (b2_ ? q4[h + 2] : q4[h]) + recv;
        }
        float send = b1_ ? r2[0] : r2[1];
        float recv = __shfl_xor_sync(0xffffffffu, send, 1);
        float val = (b1_ ? r2[1] : r2[0]) + recv;
        float mval = zmask[(size_t)i * I_ + j];
        bs[sub][j] = val + 1e8f * (mval - 1.f);
    }
    __syncthreads();

    {
        int h = wid;
        float4 x[4];
#pragma unroll
        for (int q = 0; q < 4; q++) x[q] = *(const float4*)&bs[h][q * 128 + lane * 4];
        float mx = -3.4e38f;
#pragma unroll
        for (int q = 0; q < 4; q++)
            mx = fmaxf(mx, fmaxf(fmaxf(x[q].x, x[q].y), fmaxf(x[q].z, x[q].w)));
        mx = warp_max(mx);
        float sum = 0.f;
#pragma unroll
        for (int q = 0; q < 4; q++) {
            x[q].x = __expf(x[q].x - mx); x[q].y = __expf(x[q].y - mx);
            x[q].z = __expf(x[q].z - mx); x[q].w = __expf(x[q].w - mx);
            sum += x[q].x + x[q].y + x[q].z + x[q].w;
        }
        sum = warp_sum(sum);
        float inv = 1.f / sum;
        __half* wp = d_wh + ((size_t)h * I_ + i) * I_;
#pragma unroll
        for (int q = 0; q < 4; q++) {
            __half2 h01 = __floats2half2_rn(x[q].x * inv, x[q].y * inv);
            __half2 h23 = __floats2half2_rn(x[q].z * inv, x[q].w * inv);
            *(uint2*)(wp + q * 128 + lane * 4) =
                make_uint2(*(unsigned*)&h01, *(unsigned*)&h23);
        }
    }
}

// ------- K3: fused v+g projection, fp16 MMA + ldmatrix; g staged via smem -------
__global__ void __launch_bounds__(256, 2) k_vg_h(const float* __restrict__ Wv,
                                                 const float* __restrict__ Wg,
                                                 const float* __restrict__ msk) {
    extern __shared__ __half svh[];           // As[128][72] | Ws[128][72]
    const uint32_t WS_OFF = 128 * 72;
    int t = threadIdx.x;
    int lane = t & 31, warp = t >> 5;
    int g = lane >> 2, tg = lane & 3;
    int wr = warp >> 2, wc = warp & 3;
    int rr = lane & 7, qd = lane >> 3;
    int mBase = blockIdx.y * 128, nBase = blockIdx.x * 128;
    bool isV = (blockIdx.x < 2);

#pragma unroll
    for (int q = 0; q < 4; q++) {
        int idx = q * 256 + t;
        int row = idx >> 3, u8 = idx & 7;
        uint4 v4 = *(const uint4*)(d_mh + (size_t)(mBase + row) * CM + u8 * 8);
        *(uint4*)&svh[row * 72 + u8 * 8] = v4;
    }
#pragma unroll
    for (int q = 0; q < 4; q++) {
        int idx = q * 256 + t;
        int col = idx >> 3, u8 = idx & 7;
        int gc = nBase + col;
        const float* Wp = (gc < 256) ? (Wv + (size_t)gc * CM)
                                     : (Wg + (size_t)(gc - 256) * CM);
        float4 f0 = *(const float4*)(Wp + u8 * 8);
        float4 f1 = *(const float4*)(Wp + u8 * 8 + 4);
        __half2 h0 = __floats2half2_rn(f0.x, f0.y);
        __half2 h1 = __floats2half2_rn(f0.z, f0.w);
        __half2 h2 = __floats2half2_rn(f1.x, f1.y);
        __half2 h3 = __floats2half2_rn(f1.z, f1.w);
        uint4 pk;
        pk.x = *(unsigned*)&h0; pk.y = *(unsigned*)&h1;
        pk.z = *(unsigned*)&h2; pk.w = *(unsigned*)&h3;
        *(uint4*)&svh[WS_OFF + col * 72 + u8 * 8] = pk;
    }
    __syncthreads();

    uint32_t smBase = smem_u32(svh);
    uint32_t aoff = ((wr * 64 + rr + ((qd & 1) << 3)) * 72 + ((qd >> 1) << 3)) * 2;
    uint32_t boff = WS_OFF * 2 + ((wc * 32 + rr + ((qd >> 1) << 3)) * 72 + ((qd & 1) << 3)) * 2;

    float acc[4][4][4];
#pragma unroll
    for (int a = 0; a < 4; a++)
#pragma unroll
        for (int b = 0; b < 4; b++)
#pragma unroll
            for (int c = 0; c < 4; c++) acc[a][b][c] = 0.f;

#pragma unroll
    for (int ks = 0; ks < 4; ks++) {
        uint32_t kb = ks * 32;
        uint32_t Af[4][4], Bf[4][2];
#pragma unroll
        for (int mt = 0; mt < 4; mt++)
            ldsm_x4(Af[mt][0], Af[mt][1], Af[mt][2], Af[mt][3],
                    smBase + aoff + mt * 2304 + kb);
#pragma unroll
        for (int p = 0; p < 2; p++)
            ldsm_x4(Bf[2 * p][0], Bf[2 * p][1], Bf[2 * p + 1][0], Bf[2 * p + 1][1],
                    smBase + boff + p * 2304 + kb);
#pragma unroll
        for (int mt = 0; mt < 4; mt++)
#pragma unroll
            for (int nt = 0; nt < 4; nt++)
                MMA_F16(acc[mt][nt][0], acc[mt][nt][1], acc[mt][nt][2], acc[mt][nt][3],
                        Af[mt][0], Af[mt][1], Af[mt][2], Af[mt][3],
                        Bf[nt][0], Bf[nt][1]);
    }

    if (isV) {
        // direct scatter: g-index varies j (fast dim) -> 16B segments
#pragma unroll
        for (int mt = 0; mt < 4; mt++) {
            int R0 = mBase + wr * 64 + mt * 16 + g;
            int R1 = R0 + 8;
            float mk0 = msk[R0], mk1 = msk[R1];
#pragma unroll
            for (int nt = 0; nt < 4; nt++) {
                int Cc = nBase + wc * 32 + nt * 8 + 2 * tg;
                int hh = Cc >> 5, c = Cc & 31;
                int s = R0 >> 9, j = R0 & 511;
                __half* vp = d_vh + ((size_t)hh * NN + (size_t)s * CH + c) * I_ + j;
                vp[0]       = __float2half(acc[mt][nt][0] * mk0);
                vp[I_]      = __float2half(acc[mt][nt][1] * mk0);
                vp[8]       = __float2half(acc[mt][nt][2] * mk1);
                vp[I_ + 8]  = __float2half(acc[mt][nt][3] * mk1);
            }
        }
    } else {
        // g: stage fp16 tile in smem (reuse), then fully coalesced writeout
        __syncthreads();
        __half* T = svh;                      // [128][136] halves (34.8KB < 36.9KB)
#pragma unroll
        for (int mt = 0; mt < 4; mt++) {
            int r0l = wr * 64 + mt * 16 + g, r1l = r0l + 8;
#pragma unroll
            for (int nt = 0; nt < 4; nt++) {
                int cl = wc * 32 + nt * 8 + 2 * tg;
                __half2 o0 = __floats2half2_rn(1.f / (1.f + __expf(-acc[mt][nt][0])),
                                               1.f / (1.f + __expf(-acc[mt][nt][1])));
                __half2 o1 = __floats2half2_rn(1.f / (1.f + __expf(-acc[mt][nt][2])),
                                               1.f / (1.f + __expf(-acc[mt][nt][3])));
                *(__half2*)&T[r0l * 136 + cl] = o0;
                *(__half2*)&T[r1l * 136 + cl] = o1;
            }
        }
        __syncthreads();
        int r = t >> 1, part = t & 1;
        const uint4* src = (const uint4*)&T[r * 136 + part * 64];
        uint4* dst = (uint4*)(d_gh + (size_t)(mBase + r) * HC + (nBase - 256) + part * 64);
#pragma unroll
        for (int q = 0; q < 8; q++) dst[q] = src[q];
    }
}

// ---- K4: einsum fp16 MMA; 128x128 tile, cp.async 4-stage, 2 CTAs/SM ----
// grid (m4, n64, h8), m-fast for B-tile L2 reuse.
__global__ void __launch_bounds__(256, 2) k_einsum_h() {
    extern __shared__ __half smh[];
    const uint32_t BUFB = 10240 * 2;   // bytes per stage: (128+128) rows x 40 halves
    int t = threadIdx.x, lane = t & 31, wid = t >> 5;
    int g = lane >> 2, tg = lane & 3;
    int wr = wid & 1, wc = wid >> 1;
    int rr = lane & 7, qd = lane >> 3;
    int h = blockIdx.z;
    int mBase = blockIdx.x * 128, nBase = blockIdx.y * 128;
    const __half* Ag = d_wh + ((size_t)h * I_ + mBase) * I_;
    const __half* Bg = d_vh + ((size_t)h * NN + nBase) * I_;
    __half*       C  = d_oh + ((size_t)h * I_ + mBase) * NN + nBase;

    uint32_t smBase = smem_u32(smh);
    int crow = t >> 2, cc4 = t & 3;
    const __half* srcA0 = Ag + (size_t)crow * I_ + cc4 * 8;
    const __half* srcA1 = srcA0 + (size_t)64 * I_;
    const __half* srcB0 = Bg + (size_t)crow * I_ + cc4 * 8;
    const __half* srcB1 = srcB0 + (size_t)64 * I_;
    uint32_t dA0 = (crow * 40 + cc4 * 8) * 2;
    uint32_t dA1 = dA0 + 64 * 40 * 2;
    uint32_t dB0 = dA0 + 128 * 40 * 2;
    uint32_t dB1 = dB0 + 64 * 40 * 2;

    uint32_t aoff = ((wr * 64 + rr + ((qd & 1) << 3)) * 40 + ((qd >> 1) << 3)) * 2;
    uint32_t boff = 128 * 40 * 2 + ((wc * 32 + rr + ((qd >> 1) << 3)) * 40 + ((qd & 1) << 3)) * 2;

#define EIN_ISSUE(kc) do {                                   \
        uint32_t _b = smBase + ((kc) & 3) * BUFB;            \
        cpa16(_b + dA0, srcA0 + (kc) * 32);                  \
        cpa16(_b + dA1, srcA1 + (kc) * 32);                  \
        cpa16(_b + dB0, srcB0 + (kc) * 32);                  \
        cpa16(_b + dB1, srcB1 + (kc) * 32);                  \
        CP_COMMIT();                                         \
    } while (0)

    EIN_ISSUE(0);
    EIN_ISSUE(1);
    EIN_ISSUE(2);

    float acc[4][4][4];
#pragma unroll
    for (int a = 0; a < 4; a++)
#pragma unroll
        for (int b = 0; b < 4; b++)
#pragma unroll
            for (int c = 0; c < 4; c++) acc[a][b][c] = 0.f;

#pragma unroll 1
    for (int kc = 0; kc < 16; kc++) {
        if (kc < 13) asm volatile("cp.async.wait_group 2;" ::: "memory");
        else         asm volatile("cp.async.wait_group 0;" ::: "memory");
        __syncthreads();
        if (kc < 13) EIN_ISSUE(kc + 3);
        uint32_t buf = smBase + (kc & 3) * BUFB;
#pragma unroll
        for (int ks = 0; ks < 2; ks++) {
            uint32_t kb = ks * 32;
            uint32_t Af[4][4], Bf[4][2];
#pragma unroll
            for (int mt = 0; mt < 4; mt++)
                ldsm_x4(Af[mt][0], Af[mt][1], Af[mt][2], Af[mt][3],
                        buf + aoff + mt * 1280 + kb);
#pragma unroll
            for (int p = 0; p < 2; p++)
                ldsm_x4(Bf[2 * p][0], Bf[2 * p][1], Bf[2 * p + 1][0], Bf[2 * p + 1][1],
                        buf + boff + p * 1280 + kb);
#pragma unroll
            for (int mt = 0; mt < 4; mt++)
#pragma unroll
                for (int nt = 0; nt < 4; nt++)
                    MMA_F16(acc[mt][nt][0], acc[mt][nt][1], acc[mt][nt][2], acc[mt][nt][3],
                            Af[mt][0], Af[mt][1], Af[mt][2], Af[mt][3],
                            Bf[nt][0], Bf[nt][1]);
        }
    }

#pragma unroll
    for (int mt = 0; mt < 4; mt++) {
        int r = wr * 64 + mt * 16 + g;
#pragma unroll
        for (int nt = 0; nt < 4; nt++) {
            int col = wc * 32 + nt * 8 + 2 * tg;
            __half2 h0 = __floats2half2_rn(acc[mt][nt][0], acc[mt][nt][1]);
            __half2 h1 = __floats2half2_rn(acc[mt][nt][2], acc[mt][nt][3]);
            *(__half2*)(C + (size_t)r * NN + col)       = h0;
            *(__half2*)(C + (size_t)(r + 8) * NN + col) = h1;
        }
    }
#undef EIN_ISSUE
}

// ---- K5: out = (g * gather(o)) @ W_o^T via fp16 MMA ----
__global__ void __launch_bounds__(256) k_out_h(const float* __restrict__ Wo,
                                               float* __restrict__ out) {
    extern __shared__ __half sh[];
    __half* prodA = sh;               // [64][264]
    __half* WoS   = sh + 64 * 264;    // [64][264]
    int t = threadIdx.x, lane = t & 31, wid = t >> 5;
    int g = lane >> 2, tg = lane & 3;
    int rr = lane & 7, qd = lane >> 3;
    int wm = wid & 1, wn = wid >> 1;
    int rowBase = blockIdx.x * 64;

#pragma unroll
    for (int q = 0; q < 16; q++) {
        int idx = q * 256 + t;
        int cm = idx >> 6, kf = idx & 63;
        float4 f = *(const float4*)(Wo + (size_t)cm * HC + kf * 4);
        __half2 h0 = __floats2half2_rn(f.x, f.y);
        __half2 h1 = __floats2half2_rn(f.z, f.w);
        *(uint2*)&WoS[cm * 264 + kf * 4] = make_uint2(*(unsigned*)&h0, *(unsigned*)&h1);
    }
    {
        int hh = t >> 5, c = t & 31;
#pragma unroll 8
        for (int q = 0; q < 64; q++) {
            int gr = rowBase + q;
            int s = gr >> 9, i = gr & 511;
            float gv = __half2float(d_gh[(size_t)gr * HC + t]);
            float ov = __half2float(d_oh[((size_t)hh * I_ + i) * NN + s * CH + c]);
            prodA[q * 264 + t] = __float2half(gv * ov);
        }
    }
    __syncthreads();

    uint32_t smBase = smem_u32(sh);
    uint32_t aoff = ((wm * 32 + rr + ((qd & 1) << 3)) * 264 + ((qd >> 1) << 3)) * 2;
    uint32_t boff = (64 * 264 + (wn * 16 + rr + ((qd >> 1) << 3)) * 264 + ((qd & 1) << 3)) * 2;

    float acc[2][2][4];
#pragma unroll
    for (int a = 0; a < 2; a++)
#pragma unroll
        for (int b = 0; b < 2; b++)
#pragma unroll
            for (int c = 0; c < 4; c++) acc[a][b][c] = 0.f;

#pragma unroll
    for (int ks = 0; ks < 16; ks++) {
        uint32_t kb = ks * 32;
        uint32_t Af[2][4], Bf[2][2];
#pragma unroll
        for (int mt = 0; mt < 2; mt++)
            ldsm_x4(Af[mt][0], Af[mt][1], Af[mt][2], Af[mt][3],
                    smBase + aoff + mt * (16 * 264 * 2) + kb);
        ldsm_x4(Bf[0][0], Bf[0][1], Bf[1][0], Bf[1][1], smBase + boff + kb);
#pragma unroll
        for (int mt = 0; mt < 2; mt++)
#pragma unroll
            for (int nt = 0; nt < 2; nt++)
                MMA_F16(acc[mt][nt][0], acc[mt][nt][1], acc[mt][nt][2], acc[mt][nt][3],
                        Af[mt][0], Af[mt][1], Af[mt][2], Af[mt][3],
                        Bf[nt][0], Bf[nt][1]);
    }

#pragma unroll
    for (int mt = 0; mt < 2; mt++) {
        int r0 = rowBase + wm * 32 + mt * 16 + g;
#pragma unroll
        for (int nt = 0; nt < 2; nt++) {
            int col = wn * 16 + nt * 8 + 2 * tg;
            *(float2*)(out + (size_t)r0 * CM + col) =
                make_float2(acc[mt][nt][0], acc[mt][nt][1]);
            *(float2*)(out + (size_t)(r0 + 8) * CM + col) =
                make_float2(acc[mt][nt][2], acc[mt][nt][3]);
        }
    }
}

extern "C" void kernel_launch(void* const* d_in, const int* in_sizes, int n_in,
                              void* d_out, int out_size) {
    const float* m        = (const float*)d_in[0];
    const float* z        = (const float*)d_in[1];
    const float* msa_mask = (const float*)d_in[2];
    const float* z_mask   = (const float*)d_in[3];
    const float* ln_m_g   = (const float*)d_in[4];
    const float* ln_m_b   = (const float*)d_in[5];
    const float* W_v      = (const float*)d_in[6];
    const float* W_g      = (const float*)d_in[7];
    const float* ln_z_g   = (const float*)d_in[8];
    const float* ln_z_b   = (const float*)d_in[9];
    const float* W_b      = (const float*)d_in[10];
    const float* W_o      = (const float*)d_in[11];
    float* out = (float*)d_out;

    const int SMEM_VG  = 2 * 128 * 72 * 2;            // 36864
    const int SMEM_EIN = 4 * 10240 * 2;               // 81920
    const int SMEM_OUT = 2 * 64 * 264 * 2;            // 67584
    cudaFuncSetAttribute(k_vg_h,    cudaFuncAttributeMaxDynamicSharedMemorySize, SMEM_VG);
    cudaFuncSetAttribute(k_einsum_h,cudaFuncAttributeMaxDynamicSharedMemorySize, SMEM_EIN);
    cudaFuncSetAttribute(k_out_h,   cudaFuncAttributeMaxDynamicSharedMemorySize, SMEM_OUT);

    k_ln_m<<<S_ * I_ / 8, 256>>>(m, ln_m_g, ln_m_b);                 // 0
    k_bsm<<<I_, 256>>>(z, ln_z_g, ln_z_b, W_b, z_mask);              // 1
    k_vg_h<<<dim3(4, 1024), 256, SMEM_VG>>>(W_v, W_g, msa_mask);     // 2
    k_einsum_h<<<dim3(4, 64, 8), 256, SMEM_EIN>>>();                 // 3 (profiled)
    k_out_h<<<S_ * I_ / 64, 256, SMEM_OUT>>>(W_o, out);              // 4
}

// round 12
// speedup vs baseline: 1.0396x; 1.0396x over previous
#include <cuda_runtime.h>
#include <cuda_fp16.h>
#include <math.h>
#include <cstdint>

#define S_  256
#define I_  512
#define CM  64
#define CZ  128
#define H_  8
#define CH  32
#define HC  256
#define NN  (S_*CH)   // 8192
#define EPS 1e-5f

// ---- scratch ----
__device__ __half d_mh[(size_t)S_*I_*CM];     // LN(m) fp16
__device__ __half d_vh[(size_t)H_*NN*I_];     // v fp16 [h][n][j], n = s*32+c
__device__ __half d_gh[(size_t)S_*I_*HC];     // sigmoid(g) fp16 [s*i][hc]
__device__ __half d_wh[(size_t)H_*I_*I_];     // softmax(w) fp16 [h][i][j]
__device__ __half d_oh[(size_t)H_*I_*NN];     // o fp16 [h][i][n]

__device__ __forceinline__ float warp_sum(float v) {
#pragma unroll
    for (int o = 16; o; o >>= 1) v += __shfl_xor_sync(0xffffffffu, v, o);
    return v;
}
__device__ __forceinline__ float warp_max(float v) {
#pragma unroll
    for (int o = 16; o; o >>= 1) v = fmaxf(v, __shfl_xor_sync(0xffffffffu, v, o));
    return v;
}
__device__ __forceinline__ uint32_t smem_u32(const void* p) {
    uint32_t a;
    asm("{ .reg .u64 t; cvta.to.shared.u64 t, %1; cvt.u32.u64 %0, t; }" : "=r"(a) : "l"(p));
    return a;
}
__device__ __forceinline__ void ldsm_x4(uint32_t& r0, uint32_t& r1, uint32_t& r2,
                                        uint32_t& r3, uint32_t addr) {
    asm volatile("ldmatrix.sync.aligned.m8n8.x4.shared.b16 {%0,%1,%2,%3}, [%4];"
                 : "=r"(r0), "=r"(r1), "=r"(r2), "=r"(r3) : "r"(addr));
}
__device__ __forceinline__ void cpa16(uint32_t dst, const void* src) {
    asm volatile("cp.async.cg.shared.global [%0], [%1], 16;" :: "r"(dst), "l"(src));
}
#define CP_COMMIT() asm volatile("cp.async.commit_group;" ::: "memory")

#define MMA_F16(d0,d1,d2,d3,a0,a1,a2,a3,b0,b1) \
    asm volatile("mma.sync.aligned.m16n8k16.row.col.f32.f16.f16.f32 " \
                 "{%0,%1,%2,%3},{%4,%5,%6,%7},{%8,%9},{%0,%1,%2,%3};" \
                 : "+f"(d0),"+f"(d1),"+f"(d2),"+f"(d3) \
                 : "r"(a0),"r"(a1),"r"(a2),"r"(a3),"r"(b0),"r"(b1))

// ---------------- K1: LayerNorm(m) -> fp16 ----------------
__global__ void k_ln_m(const float* __restrict__ m, const float* __restrict__ g,
                       const float* __restrict__ b) {
    int row  = blockIdx.x * 8 + (threadIdx.x >> 5);
    int lane = threadIdx.x & 31;
    const float2 v = *(const float2*)(m + (size_t)row * CM + lane * 2);
    float s  = warp_sum(v.x + v.y);
    float mu = s * (1.f / 64.f);
    float d0 = v.x - mu, d1 = v.y - mu;
    float var = warp_sum(d0 * d0 + d1 * d1) * (1.f / 64.f);
    float rs = rsqrtf(var + EPS);
    float2 gg = *(const float2*)(g + lane * 2);
    float2 bb = *(const float2*)(b + lane * 2);
    __half2 o = __floats2half2_rn(d0 * rs * gg.x + bb.x, d1 * rs * gg.y + bb.y);
    *(__half2*)(d_mh + (size_t)row * CM + lane * 2) = o;
}

// ---- K2: fused b-projection + softmax. Block per i; writes w fp16. ----
__global__ void __launch_bounds__(256) k_bsm(const float* __restrict__ z,
                                             const float* __restrict__ zg,
                                             const float* __restrict__ zb,
                                             const float* __restrict__ Wb,
                                             const float* __restrict__ zmask) {
    __shared__ __align__(16) float Wbs[H_ * CZ];
    __shared__ __align__(16) float zgs[CZ], zbs[CZ];
    __shared__ __align__(16) float bs[8][516];
    int t = threadIdx.x;
    int lane = t & 31, wid = t >> 5;
    int grp = t >> 3, sub = t & 7;
    int i = blockIdx.x;
    for (int idx = t; idx < H_ * CZ; idx += 256) Wbs[idx] = Wb[idx];
    if (t < CZ) { zgs[t] = zg[t]; zbs[t] = zb[t]; }
    __syncthreads();

#pragma unroll 1
    for (int p = 0; p < 16; p++) {
        int j = p * 32 + grp;
        const float* zp = z + ((size_t)i * I_ + j) * CZ + sub * 16;
        float4 v[4];
#pragma unroll
        for (int q = 0; q < 4; q++) v[q] = *(const float4*)(zp + q * 4);
        float s = 0.f, ss = 0.f;
#pragma unroll
        for (int q = 0; q < 4; q++) {
            s  += v[q].x + v[q].y + v[q].z + v[q].w;
            ss += v[q].x * v[q].x + v[q].y * v[q].y + v[q].z * v[q].z + v[q].w * v[q].w;
        }
#pragma unroll
        for (int o = 4; o; o >>= 1) {
            s  += __shfl_xor_sync(0xffffffffu, s, o);
            ss += __shfl_xor_sync(0xffffffffu, ss, o);
        }
        float mu = s * (1.f / 128.f);
        float var = ss * (1.f / 128.f) - mu * mu;
        float rs = rsqrtf(var + EPS);

        float xn[16];
#pragma unroll
        for (int q = 0; q < 4; q++) {
            float4 g4 = *(const float4*)(zgs + sub * 16 + q * 4);
            float4 b4 = *(const float4*)(zbs + sub * 16 + q * 4);
            xn[q * 4 + 0] = (v[q].x - mu) * rs * g4.x + b4.x;
            xn[q * 4 + 1] = (v[q].y - mu) * rs * g4.y + b4.y;
            xn[q * 4 + 2] = (v[q].z - mu) * rs * g4.z + b4.z;
            xn[q * 4 + 3] = (v[q].w - mu) * rs * g4.w + b4.w;
        }
        float pv[8];
#pragma unroll
        for (int h = 0; h < 8; h++) {
            float a = 0.f;
#pragma unroll
            for (int q = 0; q < 4; q++) {
                float4 w4 = *(const float4*)(Wbs + h * CZ + sub * 16 + q * 4);
                a += xn[q * 4 + 0] * w4.x + xn[q * 4 + 1] * w4.y +
                     xn[q * 4 + 2] * w4.z + xn[q * 4 + 3] * w4.w;
            }
            pv[h] = a;
        }
        bool b4_ = sub & 4, b2_ = sub & 2, b1_ = sub & 1;
        float q4[4];
#pragma unroll
        for (int h = 0; h < 4; h++) {
            float send = b4_ ? pv[h] : pv[h + 4];
            float recv = __shfl_xor_sync(0xffffffffu, send, 4);
            q4[h] = (b4_ ? pv[h + 4] : pv[h]) + recv;
        }
        float r2[2];
#pragma unroll
        for (int h = 0; h < 2; h++) {
            float send = b2_ ? q4[h] : q4[h + 2];
            float recv = __shfl_xor_sync(0xffffffffu, send, 2);
            r2[h] = (b2_ ? q4[h + 2] : q4[h]) + recv;
        }
        float send = b1_ ? r2[0] : r2[1];
        float recv = __shfl_xor_sync(0xffffffffu, send, 1);
        float val = (b1_ ? r2[1] : r2[0]) + recv;
        float mval = zmask[(size_t)i * I_ + j];
        bs[sub][j] = val + 1e8f * (mval - 1.f);
    }
    __syncthreads();

    {
        int h = wid;
        float4 x[4];
#pragma unroll
        for (int q = 0; q < 4; q++) x[q] = *(const float4*)&bs[h][q * 128 + lane * 4];
        float mx = -3.4e38f;
#pragma unroll
        for (int q = 0; q < 4; q++)
            mx = fmaxf(mx, fmaxf(fmaxf(x[q].x, x[q].y), fmaxf(x[q].z, x[q].w)));
        mx = warp_max(mx);
        float sum = 0.f;
#pragma unroll
        for (int q = 0; q < 4; q++) {
            x[q].x = __expf(x[q].x - mx); x[q].y = __expf(x[q].y - mx);
            x[q].z = __expf(x[q].z - mx); x[q].w = __expf(x[q].w - mx);
            sum += x[q].x + x[q].y + x[q].z + x[q].w;
        }
        sum = warp_sum(sum);
        float inv = 1.f / sum;
        __half* wp = d_wh + ((size_t)h * I_ + i) * I_;
#pragma unroll
        for (int q = 0; q < 4; q++) {
            __half2 h01 = __floats2half2_rn(x[q].x * inv, x[q].y * inv);
            __half2 h23 = __floats2half2_rn(x[q].z * inv, x[q].w * inv);
            *(uint2*)(wp + q * 128 + lane * 4) =
                make_uint2(*(unsigned*)&h01, *(unsigned*)&h23);
        }
    }
}

// ------- K3: fused v+g projection, fp16 MMA + ldmatrix; direct scatter epilogues -------
__global__ void __launch_bounds__(256, 2) k_vg_h(const float* __restrict__ Wv,
                                                 const float* __restrict__ Wg,
                                                 const float* __restrict__ msk) {
    extern __shared__ __half svh[];           // As[128][72] | Ws[128][72]
    const uint32_t WS_OFF = 128 * 72;
    int t = threadIdx.x;
    int lane = t & 31, warp = t >> 5;
    int g = lane >> 2, tg = lane & 3;
    int wr = warp >> 2, wc = warp & 3;
    int rr = lane & 7, qd = lane >> 3;
    int mBase = blockIdx.y * 128, nBase = blockIdx.x * 128;
    bool isV = (blockIdx.x < 2);

#pragma unroll
    for (int q = 0; q < 4; q++) {
        int idx = q * 256 + t;
        int row = idx >> 3, u8 = idx & 7;
        uint4 v4 = *(const uint4*)(d_mh + (size_t)(mBase + row) * CM + u8 * 8);
        *(uint4*)&svh[row * 72 + u8 * 8] = v4;
    }
#pragma unroll
    for (int q = 0; q < 4; q++) {
        int idx = q * 256 + t;
        int col = idx >> 3, u8 = idx & 7;
        int gc = nBase + col;
        const float* Wp = (gc < 256) ? (Wv + (size_t)gc * CM)
                                     : (Wg + (size_t)(gc - 256) * CM);
        float4 f0 = *(const float4*)(Wp + u8 * 8);
        float4 f1 = *(const float4*)(Wp + u8 * 8 + 4);
        __half2 h0 = __floats2half2_rn(f0.x, f0.y);
        __half2 h1 = __floats2half2_rn(f0.z, f0.w);
        __half2 h2 = __floats2half2_rn(f1.x, f1.y);
        __half2 h3 = __floats2half2_rn(f1.z, f1.w);
        uint4 pk;
        pk.x = *(unsigned*)&h0; pk.y = *(unsigned*)&h1;
        pk.z = *(unsigned*)&h2; pk.w = *(unsigned*)&h3;
        *(uint4*)&svh[WS_OFF + col * 72 + u8 * 8] = pk;
    }
    __syncthreads();

    uint32_t smBase = smem_u32(svh);
    uint32_t aoff = ((wr * 64 + rr + ((qd & 1) << 3)) * 72 + ((qd >> 1) << 3)) * 2;
    uint32_t boff = WS_OFF * 2 + ((wc * 32 + rr + ((qd >> 1) << 3)) * 72 + ((qd & 1) << 3)) * 2;

    float acc[4][4][4];
#pragma unroll
    for (int a = 0; a < 4; a++)
#pragma unroll
        for (int b = 0; b < 4; b++)
#pragma unroll
            for (int c = 0; c < 4; c++) acc[a][b][c] = 0.f;

#pragma unroll
    for (int ks = 0; ks < 4; ks++) {
        uint32_t kb = ks * 32;
        uint32_t Af[4][4], Bf[4][2];
#pragma unroll
        for (int mt = 0; mt < 4; mt++)
            ldsm_x4(Af[mt][0], Af[mt][1], Af[mt][2], Af[mt][3],
                    smBase + aoff + mt * 2304 + kb);
#pragma unroll
        for (int p = 0; p < 2; p++)
            ldsm_x4(Bf[2 * p][0], Bf[2 * p][1], Bf[2 * p + 1][0], Bf[2 * p + 1][1],
                    smBase + boff + p * 2304 + kb);
#pragma unroll
        for (int mt = 0; mt < 4; mt++)
#pragma unroll
            for (int nt = 0; nt < 4; nt++)
                MMA_F16(acc[mt][nt][0], acc[mt][nt][1], acc[mt][nt][2], acc[mt][nt][3],
                        Af[mt][0], Af[mt][1], Af[mt][2], Af[mt][3],
                        Bf[nt][0], Bf[nt][1]);
    }

    if (isV) {
#pragma unroll
        for (int mt = 0; mt < 4; mt++) {
            int R0 = mBase + wr * 64 + mt * 16 + g;
            int R1 = R0 + 8;
            float mk0 = msk[R0], mk1 = msk[R1];
#pragma unroll
            for (int nt = 0; nt < 4; nt++) {
                int Cc = nBase + wc * 32 + nt * 8 + 2 * tg;
                int hh = Cc >> 5, c = Cc & 31;
                int s = R0 >> 9, j = R0 & 511;
                __half* vp = d_vh + ((size_t)hh * NN + (size_t)s * CH + c) * I_ + j;
                vp[0]       = __float2half(acc[mt][nt][0] * mk0);
                vp[I_]      = __float2half(acc[mt][nt][1] * mk0);
                vp[8]       = __float2half(acc[mt][nt][2] * mk1);
                vp[I_ + 8]  = __float2half(acc[mt][nt][3] * mk1);
            }
        }
    } else {
#pragma unroll
        for (int mt = 0; mt < 4; mt++) {
            int R0 = mBase + wr * 64 + mt * 16 + g;
            int R1 = R0 + 8;
#pragma unroll
            for (int nt = 0; nt < 4; nt++) {
                int cg = (nBase - 256) + wc * 32 + nt * 8 + 2 * tg;
                __half2 o0 = __floats2half2_rn(1.f / (1.f + __expf(-acc[mt][nt][0])),
                                               1.f / (1.f + __expf(-acc[mt][nt][1])));
                __half2 o1 = __floats2half2_rn(1.f / (1.f + __expf(-acc[mt][nt][2])),
                                               1.f / (1.f + __expf(-acc[mt][nt][3])));
                *(__half2*)(d_gh + (size_t)R0 * HC + cg) = o0;
                *(__half2*)(d_gh + (size_t)R1 * HC + cg) = o1;
            }
        }
    }
}

// ---- K4: einsum fp16 MMA; 128x128 tile, cp.async 4-stage, 2 CTAs/SM ----
__global__ void __launch_bounds__(256, 2) k_einsum_h() {
    extern __shared__ __half smh[];
    const uint32_t BUFB = 10240 * 2;
    int t = threadIdx.x, lane = t & 31, wid = t >> 5;
    int g = lane >> 2, tg = lane & 3;
    int wr = wid & 1, wc = wid >> 1;
    int rr = lane & 7, qd = lane >> 3;
    int h = blockIdx.z;
    int mBase = blockIdx.x * 128, nBase = blockIdx.y * 128;
    const __half* Ag = d_wh + ((size_t)h * I_ + mBase) * I_;
    const __half* Bg = d_vh + ((size_t)h * NN + nBase) * I_;
    __half*       C  = d_oh + ((size_t)h * I_ + mBase) * NN + nBase;

    uint32_t smBase = smem_u32(smh);
    int crow = t >> 2, cc4 = t & 3;
    const __half* srcA0 = Ag + (size_t)crow * I_ + cc4 * 8;
    const __half* srcA1 = srcA0 + (size_t)64 * I_;
    const __half* srcB0 = Bg + (size_t)crow * I_ + cc4 * 8;
    const __half* srcB1 = srcB0 + (size_t)64 * I_;
    uint32_t dA0 = (crow * 40 + cc4 * 8) * 2;
    uint32_t dA1 = dA0 + 64 * 40 * 2;
    uint32_t dB0 = dA0 + 128 * 40 * 2;
    uint32_t dB1 = dB0 + 64 * 40 * 2;

    uint32_t aoff = ((wr * 64 + rr + ((qd & 1) << 3)) * 40 + ((qd >> 1) << 3)) * 2;
    uint32_t boff = 128 * 40 * 2 + ((wc * 32 + rr + ((qd >> 1) << 3)) * 40 + ((qd & 1) << 3)) * 2;

#define EIN_ISSUE(kc) do {                                   \
        uint32_t _b = smBase + ((kc) & 3) * BUFB;            \
        cpa16(_b + dA0, srcA0 + (kc) * 32);                  \
        cpa16(_b + dA1, srcA1 + (kc) * 32);                  \
        cpa16(_b + dB0, srcB0 + (kc) * 32);                  \
        cpa16(_b + dB1, srcB1 + (kc) * 32);                  \
        CP_COMMIT();                                         \
    } while (0)

    EIN_ISSUE(0);
    EIN_ISSUE(1);
    EIN_ISSUE(2);

    float acc[4][4][4];
#pragma unroll
    for (int a = 0; a < 4; a++)
#pragma unroll
        for (int b = 0; b < 4; b++)
#pragma unroll
            for (int c = 0; c < 4; c++) acc[a][b][c] = 0.f;

#pragma unroll 1
    for (int kc = 0; kc < 16; kc++) {
        if (kc < 13) asm volatile("cp.async.wait_group 2;" ::: "memory");
        else         asm volatile("cp.async.wait_group 0;" ::: "memory");
        __syncthreads();
        if (kc < 13) EIN_ISSUE(kc + 3);
        uint32_t buf = smBase + (kc & 3) * BUFB;
#pragma unroll
        for (int ks = 0; ks < 2; ks++) {
            uint32_t kb = ks * 32;
            uint32_t Af[4][4], Bf[4][2];
#pragma unroll
            for (int mt = 0; mt < 4; mt++)
                ldsm_x4(Af[mt][0], Af[mt][1], Af[mt][2], Af[mt][3],
                        buf + aoff + mt * 1280 + kb);
#pragma unroll
            for (int p = 0; p < 2; p++)
                ldsm_x4(Bf[2 * p][0], Bf[2 * p][1], Bf[2 * p + 1][0], Bf[2 * p + 1][1],
                        buf + boff + p * 1280 + kb);
#pragma unroll
            for (int mt = 0; mt < 4; mt++)
#pragma unroll
                for (int nt = 0; nt < 4; nt++)
                    MMA_F16(acc[mt][nt][0], acc[mt][nt][1], acc[mt][nt][2], acc[mt][nt][3],
                            Af[mt][0], Af[mt][1], Af[mt][2], Af[mt][3],
                            Bf[nt][0], Bf[nt][1]);
        }
    }

#pragma unroll
    for (int mt = 0; mt < 4; mt++) {
        int r = wr * 64 + mt * 16 + g;
#pragma unroll
        for (int nt = 0; nt < 4; nt++) {
            int col = wc * 32 + nt * 8 + 2 * tg;
            __half2 h0 = __floats2half2_rn(acc[mt][nt][0], acc[mt][nt][1]);
            __half2 h1 = __floats2half2_rn(acc[mt][nt][2], acc[mt][nt][3]);
            *(__half2*)(C + (size_t)r * NN + col)       = h0;
            *(__half2*)(C + (size_t)(r + 8) * NN + col) = h1;
        }
    }
#undef EIN_ISSUE
}

// ---- K5: out = (g * gather(o)) @ W_o^T via fp16 MMA ----
__global__ void __launch_bounds__(256) k_out_h(const float* __restrict__ Wo,
                                               float* __restrict__ out) {
    extern __shared__ __half sh[];
    __half* prodA = sh;               // [64][264]
    __half* WoS   = sh + 64 * 264;    // [64][264]
    int t = threadIdx.x, lane = t & 31, wid = t >> 5;
    int g = lane >> 2, tg = lane & 3;
    int rr = lane & 7, qd = lane >> 3;
    int wm = wid & 1, wn = wid >> 1;
    int rowBase = blockIdx.x * 64;

#pragma unroll
    for (int q = 0; q < 16; q++) {
        int idx = q * 256 + t;
        int cm = idx >> 6, kf = idx & 63;
        float4 f = *(const float4*)(Wo + (size_t)cm * HC + kf * 4);
        __half2 h0 = __floats2half2_rn(f.x, f.y);
        __half2 h1 = __floats2half2_rn(f.z, f.w);
        *(uint2*)&WoS[cm * 264 + kf * 4] = make_uint2(*(unsigned*)&h0, *(unsigned*)&h1);
    }
    {
        int hh = t >> 5, c = t & 31;
#pragma unroll 8
        for (int q = 0; q < 64; q++) {
            int gr = rowBase + q;
            int s = gr >> 9, i = gr & 511;
            float gv = __half2float(d_gh[(size_t)gr * HC + t]);
            float ov = __half2float(d_oh[((size_t)hh * I_ + i) * NN + s * CH + c]);
            prodA[q * 264 + t] = __float2half(gv * ov);
        }
    }
    __syncthreads();

    uint32_t smBase = smem_u32(sh);
    uint32_t aoff = ((wm * 32 + rr + ((qd & 1) << 3)) * 264 + ((qd >> 1) << 3)) * 2;
    uint32_t boff = (64 * 264 + (wn * 16 + rr + ((qd >> 1) << 3)) * 264 + ((qd & 1) << 3)) * 2;

    float acc[2][2][4];
#pragma unroll
    for (int a = 0; a < 2; a++)
#pragma unroll
        for (int b = 0; b < 2; b++)
#pragma unroll
            for (int c = 0; c < 4; c++) acc[a][b][c] = 0.f;

#pragma unroll
    for (int ks = 0; ks < 16; ks++) {
        uint32_t kb = ks * 32;
        uint32_t Af[2][4], Bf[2][2];
#pragma unroll
        for (int mt = 0; mt < 2; mt++)
            ldsm_x4(Af[mt][0], Af[mt][1], Af[mt][2], Af[mt][3],
                    smBase + aoff + mt * (16 * 264 * 2) + kb);
        ldsm_x4(Bf[0][0], Bf[0][1], Bf[1][0], Bf[1][1], smBase + boff + kb);
#pragma unroll
        for (int mt = 0; mt < 2; mt++)
#pragma unroll
            for (int nt = 0; nt < 2; nt++)
                MMA_F16(acc[mt][nt][0], acc[mt][nt][1], acc[mt][nt][2], acc[mt][nt][3],
                        Af[mt][0], Af[mt][1], Af[mt][2], Af[mt][3],
                        Bf[nt][0], Bf[nt][1]);
    }

#pragma unroll
    for (int mt = 0; mt < 2; mt++) {
        int r0 = rowBase + wm * 32 + mt * 16 + g;
#pragma unroll
        for (int nt = 0; nt < 2; nt++) {
            int col = wn * 16 + nt * 8 + 2 * tg;
            *(float2*)(out + (size_t)r0 * CM + col) =
                make_float2(acc[mt][nt][0], acc[mt][nt][1]);
            *(float2*)(out + (size_t)(r0 + 8) * CM + col) =
                make_float2(acc[mt][nt][2], acc[mt][nt][3]);
        }
    }
}

extern "C" void kernel_launch(void* const* d_in, const int* in_sizes, int n_in,
                              void* d_out, int out_size) {
    const float* m        = (const float*)d_in[0];
    const float* z        = (const float*)d_in[1];
    const float* msa_mask = (const float*)d_in[2];
    const float* z_mask   = (const float*)d_in[3];
    const float* ln_m_g   = (const float*)d_in[4];
    const float* ln_m_b   = (const float*)d_in[5];
    const float* W_v      = (const float*)d_in[6];
    const float* W_g      = (const float*)d_in[7];
    const float* ln_z_g   = (const float*)d_in[8];
    const float* ln_z_b   = (const float*)d_in[9];
    const float* W_b      = (const float*)d_in[10];
    const float* W_o      = (const float*)d_in[11];
    float* out = (float*)d_out;

    const int SMEM_VG  = 2 * 128 * 72 * 2;            // 36864
    const int SMEM_EIN = 4 * 10240 * 2;               // 81920
    const int SMEM_OUT = 2 * 64 * 264 * 2;            // 67584
    cudaFuncSetAttribute(k_vg_h,    cudaFuncAttributeMaxDynamicSharedMemorySize, SMEM_VG);
    cudaFuncSetAttribute(k_einsum_h,cudaFuncAttributeMaxDynamicSharedMemorySize, SMEM_EIN);
    cudaFuncSetAttribute(k_out_h,   cudaFuncAttributeMaxDynamicSharedMemorySize, SMEM_OUT);

    // bsm at idx 0 so idx-3 profile lands on k_out_h (new info), deps preserved:
    // bsm -> einsum needs d_wh; vg -> einsum needs d_vh; einsum -> out needs d_oh.
    k_bsm<<<I_, 256>>>(z, ln_z_g, ln_z_b, W_b, z_mask);              // 0
    k_ln_m<<<S_ * I_ / 8, 256>>>(m, ln_m_g, ln_m_b);                 // 1
    k_vg_h<<<dim3(4, 1024), 256, SMEM_VG>>>(W_v, W_g, msa_mask);     // 2
    k_einsum_h<<<dim3(4, 64, 8), 256, SMEM_EIN>>>();                 // 3
    k_out_h<<<S_ * I_ / 64, 256, SMEM_OUT>>>(W_o, out);              // 4
}

// round 13
// speedup vs baseline: 1.0433x; 1.0036x over previous
#include <cuda_runtime.h>
#include <cuda_fp16.h>
#include <math.h>
#include <cstdint>

#define S_  256
#define I_  512
#define CM  64
#define CZ  128
#define H_  8
#define CH  32
#define HC  256
#define NN  (S_*CH)   // 8192
#define EPS 1e-5f

// ---- scratch ----
__device__ __half d_mh[(size_t)S_*I_*CM];     // LN(m) fp16
__device__ __half d_vh[(size_t)H_*NN*I_];     // v fp16 [h][n][j], n = s*32+c
__device__ __half d_gh[(size_t)S_*I_*HC];     // sigmoid(g) fp16 [s*i][hc]
__device__ __half d_wh[(size_t)H_*I_*I_];     // softmax(w) fp16 [h][i][j]
__device__ __half d_oh[(size_t)H_*I_*NN];     // o fp16 [h][i][n]

__device__ __forceinline__ float warp_sum(float v) {
#pragma unroll
    for (int o = 16; o; o >>= 1) v += __shfl_xor_sync(0xffffffffu, v, o);
    return v;
}
__device__ __forceinline__ float warp_max(float v) {
#pragma unroll
    for (int o = 16; o; o >>= 1) v = fmaxf(v, __shfl_xor_sync(0xffffffffu, v, o));
    return v;
}
__device__ __forceinline__ uint32_t smem_u32(const void* p) {
    uint32_t a;
    asm("{ .reg .u64 t; cvta.to.shared.u64 t, %1; cvt.u32.u64 %0, t; }" : "=r"(a) : "l"(p));
    return a;
}
__device__ __forceinline__ void ldsm_x4(uint32_t& r0, uint32_t& r1, uint32_t& r2,
                                        uint32_t& r3, uint32_t addr) {
    asm volatile("ldmatrix.sync.aligned.m8n8.x4.shared.b16 {%0,%1,%2,%3}, [%4];"
                 : "=r"(r0), "=r"(r1), "=r"(r2), "=r"(r3) : "r"(addr));
}
__device__ __forceinline__ void cpa16(uint32_t dst, const void* src) {
    asm volatile("cp.async.cg.shared.global [%0], [%1], 16;" :: "r"(dst), "l"(src));
}
#define CP_COMMIT() asm volatile("cp.async.commit_group;" ::: "memory")

#define MMA_F16(d0,d1,d2,d3,a0,a1,a2,a3,b0,b1) \
    asm volatile("mma.sync.aligned.m16n8k16.row.col.f32.f16.f16.f32 " \
                 "{%0,%1,%2,%3},{%4,%5,%6,%7},{%8,%9},{%0,%1,%2,%3};" \
                 : "+f"(d0),"+f"(d1),"+f"(d2),"+f"(d3) \
                 : "r"(a0),"r"(a1),"r"(a2),"r"(a3),"r"(b0),"r"(b1))

// ---------------- K1: LayerNorm(m) -> fp16 ----------------
__global__ void k_ln_m(const float* __restrict__ m, const float* __restrict__ g,
                       const float* __restrict__ b) {
    int row  = blockIdx.x * 8 + (threadIdx.x >> 5);
    int lane = threadIdx.x & 31;
    const float2 v = *(const float2*)(m + (size_t)row * CM + lane * 2);
    float s  = warp_sum(v.x + v.y);
    float mu = s * (1.f / 64.f);
    float d0 = v.x - mu, d1 = v.y - mu;
    float var = warp_sum(d0 * d0 + d1 * d1) * (1.f / 64.f);
    float rs = rsqrtf(var + EPS);
    float2 gg = *(const float2*)(g + lane * 2);
    float2 bb = *(const float2*)(b + lane * 2);
    __half2 o = __floats2half2_rn(d0 * rs * gg.x + bb.x, d1 * rs * gg.y + bb.y);
    *(__half2*)(d_mh + (size_t)row * CM + lane * 2) = o;
}

// ---- K2: fused b-projection + softmax. Block per i; writes w fp16. ----
__global__ void __launch_bounds__(256) k_bsm(const float* __restrict__ z,
                                             const float* __restrict__ zg,
                                             const float* __restrict__ zb,
                                             const float* __restrict__ Wb,
                                             const float* __restrict__ zmask) {
    __shared__ __align__(16) float Wbs[H_ * CZ];
    __shared__ __align__(16) float zgs[CZ], zbs[CZ];
    __shared__ __align__(16) float bs[8][516];
    int t = threadIdx.x;
    int lane = t & 31, wid = t >> 5;
    int grp = t >> 3, sub = t & 7;
    int i = blockIdx.x;
    for (int idx = t; idx < H_ * CZ; idx += 256) Wbs[idx] = Wb[idx];
    if (t < CZ) { zgs[t] = zg[t]; zbs[t] = zb[t]; }
    __syncthreads();

#pragma unroll 1
    for (int p = 0; p < 16; p++) {
        int j = p * 32 + grp;
        const float* zp = z + ((size_t)i * I_ + j) * CZ + sub * 16;
        float4 v[4];
#pragma unroll
        for (int q = 0; q < 4; q++) v[q] = *(const float4*)(zp + q * 4);
        float s = 0.f, ss = 0.f;
#pragma unroll
        for (int q = 0; q < 4; q++) {
            s  += v[q].x + v[q].y + v[q].z + v[q].w;
            ss += v[q].x * v[q].x + v[q].y * v[q].y + v[q].z * v[q].z + v[q].w * v[q].w;
        }
#pragma unroll
        for (int o = 4; o; o >>= 1) {
            s  += __shfl_xor_sync(0xffffffffu, s, o);
            ss += __shfl_xor_sync(0xffffffffu, ss, o);
        }
        float mu = s * (1.f / 128.f);
        float var = ss * (1.f / 128.f) - mu * mu;
        float rs = rsqrtf(var + EPS);

        float xn[16];
#pragma unroll
        for (int q = 0; q < 4; q++) {
            float4 g4 = *(const float4*)(zgs + sub * 16 + q * 4);
            float4 b4 = *(const float4*)(zbs + sub * 16 + q * 4);
            xn[q * 4 + 0] = (v[q].x - mu) * rs * g4.x + b4.x;
            xn[q * 4 + 1] = (v[q].y - mu) * rs * g4.y + b4.y;
            xn[q * 4 + 2] = (v[q].z - mu) * rs * g4.z + b4.z;
            xn[q * 4 + 3] = (v[q].w - mu) * rs * g4.w + b4.w;
        }
        float pv[8];
#pragma unroll
        for (int h = 0; h < 8; h++) {
            float a = 0.f;
#pragma unroll
            for (int q = 0; q < 4; q++) {
                float4 w4 = *(const float4*)(Wbs + h * CZ + sub * 16 + q * 4);
                a += xn[q * 4 + 0] * w4.x + xn[q * 4 + 1] * w4.y +
                     xn[q * 4 + 2] * w4.z + xn[q * 4 + 3] * w4.w;
            }
            pv[h] = a;
        }
        bool b4_ = sub & 4, b2_ = sub & 2, b1_ = sub & 1;
        float q4[4];
#pragma unroll
        for (int h = 0; h < 4; h++) {
            float send = b4_ ? pv[h] : pv[h + 4];
            float recv = __shfl_xor_sync(0xffffffffu, send, 4);
            q4[h] = (b4_ ? pv[h + 4] : pv[h]) + recv;
        }
        float r2[2];
#pragma unroll
        for (int h = 0; h < 2; h++) {
            float send = b2_ ? q4[h] : q4[h + 2];
            float recv = __shfl_xor_sync(0xffffffffu, send, 2);
            r2[h] = (b2_ ? q4[h + 2] : q4[h]) + recv;
        }
        float send = b1_ ? r2[0] : r2[1];
        float recv = __shfl_xor_sync(0xffffffffu, send, 1);
        float val = (b1_ ? r2[1] : r2[0]) + recv;
        float mval = zmask[(size_t)i * I_ + j];
        bs[sub][j] = val + 1e8f * (mval - 1.f);
    }
    __syncthreads();

    {
        int h = wid;
        float4 x[4];
#pragma unroll
        for (int q = 0; q < 4; q++) x[q] = *(const float4*)&bs[h][q * 128 + lane * 4];
        float mx = -3.4e38f;
#pragma unroll
        for (int q = 0; q < 4; q++)
            mx = fmaxf(mx, fmaxf(fmaxf(x[q].x, x[q].y), fmaxf(x[q].z, x[q].w)));
        mx = warp_max(mx);
        float sum = 0.f;
#pragma unroll
        for (int q = 0; q < 4; q++) {
            x[q].x = __expf(x[q].x - mx); x[q].y = __expf(x[q].y - mx);
            x[q].z = __expf(x[q].z - mx); x[q].w = __expf(x[q].w - mx);
            sum += x[q].x + x[q].y + x[q].z + x[q].w;
        }
        sum = warp_sum(sum);
        float inv = 1.f / sum;
        __half* wp = d_wh + ((size_t)h * I_ + i) * I_;
#pragma unroll
        for (int q = 0; q < 4; q++) {
            __half2 h01 = __floats2half2_rn(x[q].x * inv, x[q].y * inv);
            __half2 h23 = __floats2half2_rn(x[q].z * inv, x[q].w * inv);
            *(uint2*)(wp + q * 128 + lane * 4) =
                make_uint2(*(unsigned*)&h01, *(unsigned*)&h23);
        }
    }
}

// ------- K3: fused v+g projection, fp16 MMA + ldmatrix; direct scatter epilogues -------
__global__ void __launch_bounds__(256, 2) k_vg_h(const float* __restrict__ Wv,
                                                 const float* __restrict__ Wg,
                                                 const float* __restrict__ msk) {
    extern __shared__ __half svh[];           // As[128][72] | Ws[128][72]
    const uint32_t WS_OFF = 128 * 72;
    int t = threadIdx.x;
    int lane = t & 31, warp = t >> 5;
    int g = lane >> 2, tg = lane & 3;
    int wr = warp >> 2, wc = warp & 3;
    int rr = lane & 7, qd = lane >> 3;
    int mBase = blockIdx.y * 128, nBase = blockIdx.x * 128;
    bool isV = (blockIdx.x < 2);

#pragma unroll
    for (int q = 0; q < 4; q++) {
        int idx = q * 256 + t;
        int row = idx >> 3, u8 = idx & 7;
        uint4 v4 = *(const uint4*)(d_mh + (size_t)(mBase + row) * CM + u8 * 8);
        *(uint4*)&svh[row * 72 + u8 * 8] = v4;
    }
#pragma unroll
    for (int q = 0; q < 4; q++) {
        int idx = q * 256 + t;
        int col = idx >> 3, u8 = idx & 7;
        int gc = nBase + col;
        const float* Wp = (gc < 256) ? (Wv + (size_t)gc * CM)
                                     : (Wg + (size_t)(gc - 256) * CM);
        float4 f0 = *(const float4*)(Wp + u8 * 8);
        float4 f1 = *(const float4*)(Wp + u8 * 8 + 4);
        __half2 h0 = __floats2half2_rn(f0.x, f0.y);
        __half2 h1 = __floats2half2_rn(f0.z, f0.w);
        __half2 h2 = __floats2half2_rn(f1.x, f1.y);
        __half2 h3 = __floats2half2_rn(f1.z, f1.w);
        uint4 pk;
        pk.x = *(unsigned*)&h0; pk.y = *(unsigned*)&h1;
        pk.z = *(unsigned*)&h2; pk.w = *(unsigned*)&h3;
        *(uint4*)&svh[WS_OFF + col * 72 + u8 * 8] = pk;
    }
    __syncthreads();

    uint32_t smBase = smem_u32(svh);
    uint32_t aoff = ((wr * 64 + rr + ((qd & 1) << 3)) * 72 + ((qd >> 1) << 3)) * 2;
    uint32_t boff = WS_OFF * 2 + ((wc * 32 + rr + ((qd >> 1) << 3)) * 72 + ((qd & 1) << 3)) * 2;

    float acc[4][4][4];
#pragma unroll
    for (int a = 0; a < 4; a++)
#pragma unroll
        for (int b = 0; b < 4; b++)
#pragma unroll
            for (int c = 0; c < 4; c++) acc[a][b][c] = 0.f;

#pragma unroll
    for (int ks = 0; ks < 4; ks++) {
        uint32_t kb = ks * 32;
        uint32_t Af[4][4], Bf[4][2];
#pragma unroll
        for (int mt = 0; mt < 4; mt++)
            ldsm_x4(Af[mt][0], Af[mt][1], Af[mt][2], Af[mt][3],
                    smBase + aoff + mt * 2304 + kb);
#pragma unroll
        for (int p = 0; p < 2; p++)
            ldsm_x4(Bf[2 * p][0], Bf[2 * p][1], Bf[2 * p + 1][0], Bf[2 * p + 1][1],
                    smBase + boff + p * 2304 + kb);
#pragma unroll
        for (int mt = 0; mt < 4; mt++)
#pragma unroll
            for (int nt = 0; nt < 4; nt++)
                MMA_F16(acc[mt][nt][0], acc[mt][nt][1], acc[mt][nt][2], acc[mt][nt][3],
                        Af[mt][0], Af[mt][1], Af[mt][2], Af[mt][3],
                        Bf[nt][0], Bf[nt][1]);
    }

    if (isV) {
#pragma unroll
        for (int mt = 0; mt < 4; mt++) {
            int R0 = mBase + wr * 64 + mt * 16 + g;
            int R1 = R0 + 8;
            float mk0 = msk[R0], mk1 = msk[R1];
#pragma unroll
            for (int nt = 0; nt < 4; nt++) {
                int Cc = nBase + wc * 32 + nt * 8 + 2 * tg;
                int hh = Cc >> 5, c = Cc & 31;
                int s = R0 >> 9, j = R0 & 511;
                __half* vp = d_vh + ((size_t)hh * NN + (size_t)s * CH + c) * I_ + j;
                vp[0]       = __float2half(acc[mt][nt][0] * mk0);
                vp[I_]      = __float2half(acc[mt][nt][1] * mk0);
                vp[8]       = __float2half(acc[mt][nt][2] * mk1);
                vp[I_ + 8]  = __float2half(acc[mt][nt][3] * mk1);
            }
        }
    } else {
#pragma unroll
        for (int mt = 0; mt < 4; mt++) {
            int R0 = mBase + wr * 64 + mt * 16 + g;
            int R1 = R0 + 8;
#pragma unroll
            for (int nt = 0; nt < 4; nt++) {
                int cg = (nBase - 256) + wc * 32 + nt * 8 + 2 * tg;
                __half2 o0 = __floats2half2_rn(1.f / (1.f + __expf(-acc[mt][nt][0])),
                                               1.f / (1.f + __expf(-acc[mt][nt][1])));
                __half2 o1 = __floats2half2_rn(1.f / (1.f + __expf(-acc[mt][nt][2])),
                                               1.f / (1.f + __expf(-acc[mt][nt][3])));
                *(__half2*)(d_gh + (size_t)R0 * HC + cg) = o0;
                *(__half2*)(d_gh + (size_t)R1 * HC + cg) = o1;
            }
        }
    }
}

// ---- K4: einsum fp16 MMA; 128x128 tile, BK=64, cp.async 3-stage, 2 CTAs/SM ----
// grid (m4, n64, h8), m-fast for B-tile L2 reuse. Stage stride 72 (verified in k_vg_h).
__global__ void __launch_bounds__(256, 2) k_einsum_h() {
    extern __shared__ __half smh[];
    const uint32_t BUFB = 256 * 72 * 2;   // 36864 B per stage (128 A + 128 B rows)
    int t = threadIdx.x, lane = t & 31, wid = t >> 5;
    int g = lane >> 2, tg = lane & 3;
    int wr = wid & 1, wc = wid >> 1;
    int rr = lane & 7, qd = lane >> 3;
    int h = blockIdx.z;
    int mBase = blockIdx.x * 128, nBase = blockIdx.y * 128;
    const __half* Ag = d_wh + ((size_t)h * I_ + mBase) * I_;
    const __half* Bg = d_vh + ((size_t)h * NN + nBase) * I_;
    __half*       C  = d_oh + ((size_t)h * I_ + mBase) * NN + nBase;

    uint32_t smBase = smem_u32(smh);
    int crow = t >> 2, cc4 = t & 3;
    const __half* srcA0 = Ag + (size_t)crow * I_;
    const __half* srcA1 = srcA0 + (size_t)64 * I_;
    const __half* srcB0 = Bg + (size_t)crow * I_;
    const __half* srcB1 = srcB0 + (size_t)64 * I_;
    uint32_t dA0a = (crow * 72 + cc4 * 8) * 2;
    uint32_t dA0b = (crow * 72 + (cc4 + 4) * 8) * 2;
    uint32_t dA1a = dA0a + 64 * 72 * 2;
    uint32_t dA1b = dA0b + 64 * 72 * 2;
    uint32_t BOFF = 128 * 72 * 2;   // 18432

    uint32_t aoff = ((wr * 64 + rr + ((qd & 1) << 3)) * 72 + ((qd >> 1) << 3)) * 2;
    uint32_t boff = BOFF + ((wc * 32 + rr + ((qd >> 1) << 3)) * 72 + ((qd & 1) << 3)) * 2;

#define EIN_ISSUE(kc) do {                                               \
        uint32_t _b = smBase + ((kc) % 3) * BUFB;                        \
        int _k = (kc) * 64;                                              \
        cpa16(_b + dA0a,        srcA0 + _k + cc4 * 8);                   \
        cpa16(_b + dA0b,        srcA0 + _k + (cc4 + 4) * 8);             \
        cpa16(_b + dA1a,        srcA1 + _k + cc4 * 8);                   \
        cpa16(_b + dA1b,        srcA1 + _k + (cc4 + 4) * 8);             \
        cpa16(_b + BOFF + dA0a, srcB0 + _k + cc4 * 8);                   \
        cpa16(_b + BOFF + dA0b, srcB0 + _k + (cc4 + 4) * 8);             \
        cpa16(_b + BOFF + dA1a, srcB1 + _k + cc4 * 8);                   \
        cpa16(_b + BOFF + dA1b, srcB1 + _k + (cc4 + 4) * 8);             \
        CP_COMMIT();                                                     \
    } while (0)

    EIN_ISSUE(0);
    EIN_ISSUE(1);

    float acc[4][4][4];
#pragma unroll
    for (int a = 0; a < 4; a++)
#pragma unroll
        for (int b = 0; b < 4; b++)
#pragma unroll
            for (int c = 0; c < 4; c++) acc[a][b][c] = 0.f;

#pragma unroll 1
    for (int kc = 0; kc < 8; kc++) {
        if (kc < 7) asm volatile("cp.async.wait_group 1;" ::: "memory");
        else        asm volatile("cp.async.wait_group 0;" ::: "memory");
        __syncthreads();
        if (kc < 6) EIN_ISSUE(kc + 2);
        uint32_t buf = smBase + (kc % 3) * BUFB;
#pragma unroll
        for (int ks = 0; ks < 4; ks++) {
            uint32_t kb = ks * 32;
            uint32_t Af[4][4], Bf[4][2];
#pragma unroll
            for (int mt = 0; mt < 4; mt++)
                ldsm_x4(Af[mt][0], Af[mt][1], Af[mt][2], Af[mt][3],
                        buf + aoff + mt * 2304 + kb);
#pragma unroll
            for (int p = 0; p < 2; p++)
                ldsm_x4(Bf[2 * p][0], Bf[2 * p][1], Bf[2 * p + 1][0], Bf[2 * p + 1][1],
                        buf + boff + p * 2304 + kb);
#pragma unroll
            for (int mt = 0; mt < 4; mt++)
#pragma unroll
                for (int nt = 0; nt < 4; nt++)
                    MMA_F16(acc[mt][nt][0], acc[mt][nt][1], acc[mt][nt][2], acc[mt][nt][3],
                            Af[mt][0], Af[mt][1], Af[mt][2], Af[mt][3],
                            Bf[nt][0], Bf[nt][1]);
        }
    }

#pragma unroll
    for (int mt = 0; mt < 4; mt++) {
        int r = wr * 64 + mt * 16 + g;
#pragma unroll
        for (int nt = 0; nt < 4; nt++) {
            int col = wc * 32 + nt * 8 + 2 * tg;
            __half2 h0 = __floats2half2_rn(acc[mt][nt][0], acc[mt][nt][1]);
            __half2 h1 = __floats2half2_rn(acc[mt][nt][2], acc[mt][nt][3]);
            *(__half2*)(C + (size_t)r * NN + col)       = h0;
            *(__half2*)(C + (size_t)(r + 8) * NN + col) = h1;
        }
    }
#undef EIN_ISSUE
}

// ---- K5: out = (g * gather(o)) @ W_o^T via fp16 MMA ----
__global__ void __launch_bounds__(256) k_out_h(const float* __restrict__ Wo,
                                               float* __restrict__ out) {
    extern __shared__ __half sh[];
    __half* prodA = sh;               // [64][264]
    __half* WoS   = sh + 64 * 264;    // [64][264]
    int t = threadIdx.x, lane = t & 31, wid = t >> 5;
    int g = lane >> 2, tg = lane & 3;
    int rr = lane & 7, qd = lane >> 3;
    int wm = wid & 1, wn = wid >> 1;
    int rowBase = blockIdx.x * 64;

#pragma unroll
    for (int q = 0; q < 16; q++) {
        int idx = q * 256 + t;
        int cm = idx >> 6, kf = idx & 63;
        float4 f = *(const float4*)(Wo + (size_t)cm * HC + kf * 4);
        __half2 h0 = __floats2half2_rn(f.x, f.y);
        __half2 h1 = __floats2half2_rn(f.z, f.w);
        *(uint2*)&WoS[cm * 264 + kf * 4] = make_uint2(*(unsigned*)&h0, *(unsigned*)&h1);
    }
    {
        int hh = t >> 5, c = t & 31;
#pragma unroll 8
        for (int q = 0; q < 64; q++) {
            int gr = rowBase + q;
            int s = gr >> 9, i = gr & 511;
            float gv = __half2float(d_gh[(size_t)gr * HC + t]);
            float ov = __half2float(d_oh[((size_t)hh * I_ + i) * NN + s * CH + c]);
            prodA[q * 264 + t] = __float2half(gv * ov);
        }
    }
    __syncthreads();

    uint32_t smBase = smem_u32(sh);
    uint32_t aoff = ((wm * 32 + rr + ((qd & 1) << 3)) * 264 + ((qd >> 1) << 3)) * 2;
    uint32_t boff = (64 * 264 + (wn * 16 + rr + ((qd >> 1) << 3)) * 264 + ((qd & 1) << 3)) * 2;

    float acc[2][2][4];
#pragma unroll
    for (int a = 0; a < 2; a++)
#pragma unroll
        for (int b = 0; b < 2; b++)
#pragma unroll
            for (int c = 0; c < 4; c++) acc[a][b][c] = 0.f;

#pragma unroll
    for (int ks = 0; ks < 16; ks++) {
        uint32_t kb = ks * 32;
        uint32_t Af[2][4], Bf[2][2];
#pragma unroll
        for (int mt = 0; mt < 2; mt++)
            ldsm_x4(Af[mt][0], Af[mt][1], Af[mt][2], Af[mt][3],
                    smBase + aoff + mt * (16 * 264 * 2) + kb);
        ldsm_x4(Bf[0][0], Bf[0][1], Bf[1][0], Bf[1][1], smBase + boff + kb);
#pragma unroll
        for (int mt = 0; mt < 2; mt++)
#pragma unroll
            for (int nt = 0; nt < 2; nt++)
                MMA_F16(acc[mt][nt][0], acc[mt][nt][1], acc[mt][nt][2], acc[mt][nt][3],
                        Af[mt][0], Af[mt][1], Af[mt][2], Af[mt][3],
                        Bf[nt][0], Bf[nt][1]);
    }

#pragma unroll
    for (int mt = 0; mt < 2; mt++) {
        int r0 = rowBase + wm * 32 + mt * 16 + g;
#pragma unroll
        for (int nt = 0; nt < 2; nt++) {
            int col = wn * 16 + nt * 8 + 2 * tg;
            *(float2*)(out + (size_t)r0 * CM + col) =
                make_float2(acc[mt][nt][0], acc[mt][nt][1]);
            *(float2*)(out + (size_t)(r0 + 8) * CM + col) =
                make_float2(acc[mt][nt][2], acc[mt][nt][3]);
        }
    }
}

extern "C" void kernel_launch(void* const* d_in, const int* in_sizes, int n_in,
                              void* d_out, int out_size) {
    const float* m        = (const float*)d_in[0];
    const float* z        = (const float*)d_in[1];
    const float* msa_mask = (const float*)d_in[2];
    const float* z_mask   = (const float*)d_in[3];
    const float* ln_m_g   = (const float*)d_in[4];
    const float* ln_m_b   = (const float*)d_in[5];
    const float* W_v      = (const float*)d_in[6];
    const float* W_g      = (const float*)d_in[7];
    const float* ln_z_g   = (const float*)d_in[8];
    const float* ln_z_b   = (const float*)d_in[9];
    const float* W_b      = (const float*)d_in[10];
    const float* W_o      = (const float*)d_in[11];
    float* out = (float*)d_out;

    const int SMEM_VG  = 2 * 128 * 72 * 2;            // 36864
    const int SMEM_EIN = 3 * 256 * 72 * 2;            // 110592
    const int SMEM_OUT = 2 * 64 * 264 * 2;            // 67584
    cudaFuncSetAttribute(k_vg_h,    cudaFuncAttributeMaxDynamicSharedMemorySize, SMEM_VG);
    cudaFuncSetAttribute(k_einsum_h,cudaFuncAttributeMaxDynamicSharedMemorySize, SMEM_EIN);
    cudaFuncSetAttribute(k_out_h,   cudaFuncAttributeMaxDynamicSharedMemorySize, SMEM_OUT);

    k_bsm<<<I_, 256>>>(z, ln_z_g, ln_z_b, W_b, z_mask);              // 0
    k_ln_m<<<S_ * I_ / 8, 256>>>(m, ln_m_g, ln_m_b);                 // 1
    k_vg_h<<<dim3(4, 1024), 256, SMEM_VG>>>(W_v, W_g, msa_mask);     // 2
    k_einsum_h<<<dim3(4, 64, 8), 256, SMEM_EIN>>>();                 // 3 (profiled)
    k_out_h<<<S_ * I_ / 64, 256, SMEM_OUT>>>(W_o, out);              // 4
}

// round 14
// speedup vs baseline: 1.0809x; 1.0360x over previous
#include <cuda_runtime.h>
#include <cuda_fp16.h>
#include <math.h>
#include <cstdint>

#define S_  256
#define I_  512
#define CM  64
#define CZ  128
#define H_  8
#define CH  32
#define HC  256
#define NN  (S_*CH)   // 8192
#define EPS 1e-5f

// ---- scratch ----
__device__ __half d_mh[(size_t)S_*I_*CM];     // LN(m) fp16
__device__ __half d_vh[(size_t)H_*NN*I_];     // v fp16 [h][n][j], n = s*32+c
__device__ __half d_gh[(size_t)S_*I_*HC];     // sigmoid(g) fp16 [s*i][hc]
__device__ __half d_wh[(size_t)H_*I_*I_];     // softmax(w) fp16 [h][i][j]
__device__ __half d_oh[(size_t)H_*I_*NN];     // o fp16 [h][i][n]

__device__ __forceinline__ float warp_sum(float v) {
#pragma unroll
    for (int o = 16; o; o >>= 1) v += __shfl_xor_sync(0xffffffffu, v, o);
    return v;
}
__device__ __forceinline__ float warp_max(float v) {
#pragma unroll
    for (int o = 16; o; o >>= 1) v = fmaxf(v, __shfl_xor_sync(0xffffffffu, v, o));
    return v;
}
__device__ __forceinline__ uint32_t smem_u32(const void* p) {
    uint32_t a;
    asm("{ .reg .u64 t; cvta.to.shared.u64 t, %1; cvt.u32.u64 %0, t; }" : "=r"(a) : "l"(p));
    return a;
}
__device__ __forceinline__ void ldsm_x4(uint32_t& r0, uint32_t& r1, uint32_t& r2,
                                        uint32_t& r3, uint32_t addr) {
    asm volatile("ldmatrix.sync.aligned.m8n8.x4.shared.b16 {%0,%1,%2,%3}, [%4];"
                 : "=r"(r0), "=r"(r1), "=r"(r2), "=r"(r3) : "r"(addr));
}
__device__ __forceinline__ void cpa16(uint32_t dst, const void* src) {
    asm volatile("cp.async.cg.shared.global [%0], [%1], 16;" :: "r"(dst), "l"(src));
}
#define CP_COMMIT() asm volatile("cp.async.commit_group;" ::: "memory")

#define MMA_F16(d0,d1,d2,d3,a0,a1,a2,a3,b0,b1) \
    asm volatile("mma.sync.aligned.m16n8k16.row.col.f32.f16.f16.f32 " \
                 "{%0,%1,%2,%3},{%4,%5,%6,%7},{%8,%9},{%0,%1,%2,%3};" \
                 : "+f"(d0),"+f"(d1),"+f"(d2),"+f"(d3) \
                 : "r"(a0),"r"(a1),"r"(a2),"r"(a3),"r"(b0),"r"(b1))

// ---- K1: STITCHED — blocks [0,512): b-projection+softmax; blocks [512,...): LN(m) ----
__global__ void __launch_bounds__(256) k_bsm_ln(const float* __restrict__ z,
                                                const float* __restrict__ zg,
                                                const float* __restrict__ zb,
                                                const float* __restrict__ Wb,
                                                const float* __restrict__ zmask,
                                                const float* __restrict__ m,
                                                const float* __restrict__ lng,
                                                const float* __restrict__ lnb) {
    __shared__ __align__(16) float Wbs[H_ * CZ];
    __shared__ __align__(16) float zgs[CZ], zbs[CZ];
    __shared__ __align__(16) float bs[8][516];
    int t = threadIdx.x;
    int lane = t & 31, wid = t >> 5;

    if (blockIdx.x >= I_) {
        // --- LayerNorm(m) role ---
        int row  = (blockIdx.x - I_) * 8 + wid;
        const float2 v = *(const float2*)(m + (size_t)row * CM + lane * 2);
        float s  = warp_sum(v.x + v.y);
        float mu = s * (1.f / 64.f);
        float d0 = v.x - mu, d1 = v.y - mu;
        float var = warp_sum(d0 * d0 + d1 * d1) * (1.f / 64.f);
        float rs = rsqrtf(var + EPS);
        float2 gg = *(const float2*)(lng + lane * 2);
        float2 bb = *(const float2*)(lnb + lane * 2);
        __half2 o = __floats2half2_rn(d0 * rs * gg.x + bb.x, d1 * rs * gg.y + bb.y);
        *(__half2*)(d_mh + (size_t)row * CM + lane * 2) = o;
        return;
    }

    // --- b-projection + softmax role ---
    int grp = t >> 3, sub = t & 7;
    int i = blockIdx.x;
    for (int idx = t; idx < H_ * CZ; idx += 256) Wbs[idx] = Wb[idx];
    if (t < CZ) { zgs[t] = zg[t]; zbs[t] = zb[t]; }
    __syncthreads();

#pragma unroll 1
    for (int p = 0; p < 16; p++) {
        int j = p * 32 + grp;
        const float* zp = z + ((size_t)i * I_ + j) * CZ + sub * 16;
        float4 v[4];
#pragma unroll
        for (int q = 0; q < 4; q++) v[q] = *(const float4*)(zp + q * 4);
        float s = 0.f, ss = 0.f;
#pragma unroll
        for (int q = 0; q < 4; q++) {
            s  += v[q].x + v[q].y + v[q].z + v[q].w;
            ss += v[q].x * v[q].x + v[q].y * v[q].y + v[q].z * v[q].z + v[q].w * v[q].w;
        }
#pragma unroll
        for (int o = 4; o; o >>= 1) {
            s  += __shfl_xor_sync(0xffffffffu, s, o);
            ss += __shfl_xor_sync(0xffffffffu, ss, o);
        }
        float mu = s * (1.f / 128.f);
        float var = ss * (1.f / 128.f) - mu * mu;
        float rs = rsqrtf(var + EPS);

        float xn[16];
#pragma unroll
        for (int q = 0; q < 4; q++) {
            float4 g4 = *(const float4*)(zgs + sub * 16 + q * 4);
            float4 b4 = *(const float4*)(zbs + sub * 16 + q * 4);
            xn[q * 4 + 0] = (v[q].x - mu) * rs * g4.x + b4.x;
            xn[q * 4 + 1] = (v[q].y - mu) * rs * g4.y + b4.y;
            xn[q * 4 + 2] = (v[q].z - mu) * rs * g4.z + b4.z;
            xn[q * 4 + 3] = (v[q].w - mu) * rs * g4.w + b4.w;
        }
        float pv[8];
#pragma unroll
        for (int h = 0; h < 8; h++) {
            float a = 0.f;
#pragma unroll
            for (int q = 0; q < 4; q++) {
                float4 w4 = *(const float4*)(Wbs + h * CZ + sub * 16 + q * 4);
                a += xn[q * 4 + 0] * w4.x + xn[q * 4 + 1] * w4.y +
                     xn[q * 4 + 2] * w4.z + xn[q * 4 + 3] * w4.w;
            }
            pv[h] = a;
        }
        bool b4_ = sub & 4, b2_ = sub & 2, b1_ = sub & 1;
        float q4[4];
#pragma unroll
        for (int h = 0; h < 4; h++) {
            float send = b4_ ? pv[h] : pv[h + 4];
            float recv = __shfl_xor_sync(0xffffffffu, send, 4);
            q4[h] = (b4_ ? pv[h + 4] : pv[h]) + recv;
        }
        float r2[2];
#pragma unroll
        for (int h = 0; h < 2; h++) {
            float send = b2_ ? q4[h] : q4[h + 2];
            float recv = __shfl_xor_sync(0xffffffffu, send, 2);
            r2[h] = (b2_ ? q4[h + 2] : q4[h]) + recv;
        }
        float send = b1_ ? r2[0] : r2[1];
        float recv = __shfl_xor_sync(0xffffffffu, send, 1);
        float val = (b1_ ? r2[1] : r2[0]) + recv;
        float mval = zmask[(size_t)i * I_ + j];
        bs[sub][j] = val + 1e8f * (mval - 1.f);
    }
    __syncthreads();

    {
        int h = wid;
        float4 x[4];
#pragma unroll
        for (int q = 0; q < 4; q++) x[q] = *(const float4*)&bs[h][q * 128 + lane * 4];
        float mx = -3.4e38f;
#pragma unroll
        for (int q = 0; q < 4; q++)
            mx = fmaxf(mx, fmaxf(fmaxf(x[q].x, x[q].y), fmaxf(x[q].z, x[q].w)));
        mx = warp_max(mx);
        float sum = 0.f;
#pragma unroll
        for (int q = 0; q < 4; q++) {
            x[q].x = __expf(x[q].x - mx); x[q].y = __expf(x[q].y - mx);
            x[q].z = __expf(x[q].z - mx); x[q].w = __expf(x[q].w - mx);
            sum += x[q].x + x[q].y + x[q].z + x[q].w;
        }
        sum = warp_sum(sum);
        float inv = 1.f / sum;
        __half* wp = d_wh + ((size_t)h * I_ + i) * I_;
#pragma unroll
        for (int q = 0; q < 4; q++) {
            __half2 h01 = __floats2half2_rn(x[q].x * inv, x[q].y * inv);
            __half2 h23 = __floats2half2_rn(x[q].z * inv, x[q].w * inv);
            *(uint2*)(wp + q * 128 + lane * 4) =
                make_uint2(*(unsigned*)&h01, *(unsigned*)&h23);
        }
    }
}

// ------- K2: fused v+g projection, fp16 MMA + ldmatrix; direct scatter epilogues -------
__global__ void __launch_bounds__(256, 2) k_vg_h(const float* __restrict__ Wv,
                                                 const float* __restrict__ Wg,
                                                 const float* __restrict__ msk) {
    extern __shared__ __half svh[];           // As[128][72] | Ws[128][72]
    const uint32_t WS_OFF = 128 * 72;
    int t = threadIdx.x;
    int lane = t & 31, warp = t >> 5;
    int g = lane >> 2, tg = lane & 3;
    int wr = warp >> 2, wc = warp & 3;
    int rr = lane & 7, qd = lane >> 3;
    int mBase = blockIdx.y * 128, nBase = blockIdx.x * 128;
    bool isV = (blockIdx.x < 2);

#pragma unroll
    for (int q = 0; q < 4; q++) {
        int idx = q * 256 + t;
        int row = idx >> 3, u8 = idx & 7;
        uint4 v4 = *(const uint4*)(d_mh + (size_t)(mBase + row) * CM + u8 * 8);
        *(uint4*)&svh[row * 72 + u8 * 8] = v4;
    }
#pragma unroll
    for (int q = 0; q < 4; q++) {
        int idx = q * 256 + t;
        int col = idx >> 3, u8 = idx & 7;
        int gc = nBase + col;
        const float* Wp = (gc < 256) ? (Wv + (size_t)gc * CM)
                                     : (Wg + (size_t)(gc - 256) * CM);
        float4 f0 = *(const float4*)(Wp + u8 * 8);
        float4 f1 = *(const float4*)(Wp + u8 * 8 + 4);
        __half2 h0 = __floats2half2_rn(f0.x, f0.y);
        __half2 h1 = __floats2half2_rn(f0.z, f0.w);
        __half2 h2 = __floats2half2_rn(f1.x, f1.y);
        __half2 h3 = __floats2half2_rn(f1.z, f1.w);
        uint4 pk;
        pk.x = *(unsigned*)&h0; pk.y = *(unsigned*)&h1;
        pk.z = *(unsigned*)&h2; pk.w = *(unsigned*)&h3;
        *(uint4*)&svh[WS_OFF + col * 72 + u8 * 8] = pk;
    }
    __syncthreads();

    uint32_t smBase = smem_u32(svh);
    uint32_t aoff = ((wr * 64 + rr + ((qd & 1) << 3)) * 72 + ((qd >> 1) << 3)) * 2;
    uint32_t boff = WS_OFF * 2 + ((wc * 32 + rr + ((qd >> 1) << 3)) * 72 + ((qd & 1) << 3)) * 2;

    float acc[4][4][4];
#pragma unroll
    for (int a = 0; a < 4; a++)
#pragma unroll
        for (int b = 0; b < 4; b++)
#pragma unroll
            for (int c = 0; c < 4; c++) acc[a][b][c] = 0.f;

#pragma unroll
    for (int ks = 0; ks < 4; ks++) {
        uint32_t kb = ks * 32;
        uint32_t Af[4][4], Bf[4][2];
#pragma unroll
        for (int mt = 0; mt < 4; mt++)
            ldsm_x4(Af[mt][0], Af[mt][1], Af[mt][2], Af[mt][3],
                    smBase + aoff + mt * 2304 + kb);
#pragma unroll
        for (int p = 0; p < 2; p++)
            ldsm_x4(Bf[2 * p][0], Bf[2 * p][1], Bf[2 * p + 1][0], Bf[2 * p + 1][1],
                    smBase + boff + p * 2304 + kb);
#pragma unroll
        for (int mt = 0; mt < 4; mt++)
#pragma unroll
            for (int nt = 0; nt < 4; nt++)
                MMA_F16(acc[mt][nt][0], acc[mt][nt][1], acc[mt][nt][2], acc[mt][nt][3],
                        Af[mt][0], Af[mt][1], Af[mt][2], Af[mt][3],
                        Bf[nt][0], Bf[nt][1]);
    }

    if (isV) {
#pragma unroll
        for (int mt = 0; mt < 4; mt++) {
            int R0 = mBase + wr * 64 + mt * 16 + g;
            int R1 = R0 + 8;
            float mk0 = msk[R0], mk1 = msk[R1];
#pragma unroll
            for (int nt = 0; nt < 4; nt++) {
                int Cc = nBase + wc * 32 + nt * 8 + 2 * tg;
                int hh = Cc >> 5, c = Cc & 31;
                int s = R0 >> 9, j = R0 & 511;
                __half* vp = d_vh + ((size_t)hh * NN + (size_t)s * CH + c) * I_ + j;
                vp[0]       = __float2half(acc[mt][nt][0] * mk0);
                vp[I_]      = __float2half(acc[mt][nt][1] * mk0);
                vp[8]       = __float2half(acc[mt][nt][2] * mk1);
                vp[I_ + 8]  = __float2half(acc[mt][nt][3] * mk1);
            }
        }
    } else {
#pragma unroll
        for (int mt = 0; mt < 4; mt++) {
            int R0 = mBase + wr * 64 + mt * 16 + g;
            int R1 = R0 + 8;
#pragma unroll
            for (int nt = 0; nt < 4; nt++) {
                int cg = (nBase - 256) + wc * 32 + nt * 8 + 2 * tg;
                __half2 o0 = __floats2half2_rn(1.f / (1.f + __expf(-acc[mt][nt][0])),
                                               1.f / (1.f + __expf(-acc[mt][nt][1])));
                __half2 o1 = __floats2half2_rn(1.f / (1.f + __expf(-acc[mt][nt][2])),
                                               1.f / (1.f + __expf(-acc[mt][nt][3])));
                *(__half2*)(d_gh + (size_t)R0 * HC + cg) = o0;
                *(__half2*)(d_gh + (size_t)R1 * HC + cg) = o1;
            }
        }
    }
}

// ---- K3: einsum fp16 MMA; 128x128 tile, BK=64, cp.async 3-stage, 2 CTAs/SM ----
__global__ void __launch_bounds__(256, 2) k_einsum_h() {
    extern __shared__ __half smh[];
    const uint32_t BUFB = 256 * 72 * 2;
    int t = threadIdx.x, lane = t & 31, wid = t >> 5;
    int g = lane >> 2, tg = lane & 3;
    int wr = wid & 1, wc = wid >> 1;
    int rr = lane & 7, qd = lane >> 3;
    int h = blockIdx.z;
    int mBase = blockIdx.x * 128, nBase = blockIdx.y * 128;
    const __half* Ag = d_wh + ((size_t)h * I_ + mBase) * I_;
    const __half* Bg = d_vh + ((size_t)h * NN + nBase) * I_;
    __half*       C  = d_oh + ((size_t)h * I_ + mBase) * NN + nBase;

    uint32_t smBase = smem_u32(smh);
    int crow = t >> 2, cc4 = t & 3;
    const __half* srcA0 = Ag + (size_t)crow * I_;
    const __half* srcA1 = srcA0 + (size_t)64 * I_;
    const __half* srcB0 = Bg + (size_t)crow * I_;
    const __half* srcB1 = srcB0 + (size_t)64 * I_;
    uint32_t dA0a = (crow * 72 + cc4 * 8) * 2;
    uint32_t dA0b = (crow * 72 + (cc4 + 4) * 8) * 2;
    uint32_t dA1a = dA0a + 64 * 72 * 2;
    uint32_t dA1b = dA0b + 64 * 72 * 2;
    uint32_t BOFF = 128 * 72 * 2;

    uint32_t aoff = ((wr * 64 + rr + ((qd & 1) << 3)) * 72 + ((qd >> 1) << 3)) * 2;
    uint32_t boff = BOFF + ((wc * 32 + rr + ((qd >> 1) << 3)) * 72 + ((qd & 1) << 3)) * 2;

#define EIN_ISSUE(kc) do {                                               \
        uint32_t _b = smBase + ((kc) % 3) * BUFB;                        \
        int _k = (kc) * 64;                                              \
        cpa16(_b + dA0a,        srcA0 + _k + cc4 * 8);                   \
        cpa16(_b + dA0b,        srcA0 + _k + (cc4 + 4) * 8);             \
        cpa16(_b + dA1a,        srcA1 + _k + cc4 * 8);                   \
        cpa16(_b + dA1b,        srcA1 + _k + (cc4 + 4) * 8);             \
        cpa16(_b + BOFF + dA0a, srcB0 + _k + cc4 * 8);                   \
        cpa16(_b + BOFF + dA0b, srcB0 + _k + (cc4 + 4) * 8);             \
        cpa16(_b + BOFF + dA1a, srcB1 + _k + cc4 * 8);                   \
        cpa16(_b + BOFF + dA1b, srcB1 + _k + (cc4 + 4) * 8);             \
        CP_COMMIT();                                                     \
    } while (0)

    EIN_ISSUE(0);
    EIN_ISSUE(1);

    float acc[4][4][4];
#pragma unroll
    for (int a = 0; a < 4; a++)
#pragma unroll
        for (int b = 0; b < 4; b++)
#pragma unroll
            for (int c = 0; c < 4; c++) acc[a][b][c] = 0.f;

#pragma unroll 1
    for (int kc = 0; kc < 8; kc++) {
        if (kc < 7) asm volatile("cp.async.wait_group 1;" ::: "memory");
        else        asm volatile("cp.async.wait_group 0;" ::: "memory");
        __syncthreads();
        if (kc < 6) EIN_ISSUE(kc + 2);
        uint32_t buf = smBase + (kc % 3) * BUFB;
#pragma unroll
        for (int ks = 0; ks < 4; ks++) {
            uint32_t kb = ks * 32;
            uint32_t Af[4][4], Bf[4][2];
#pragma unroll
            for (int mt = 0; mt < 4; mt++)
                ldsm_x4(Af[mt][0], Af[mt][1], Af[mt][2], Af[mt][3],
                        buf + aoff + mt * 2304 + kb);
#pragma unroll
            for (int p = 0; p < 2; p++)
                ldsm_x4(Bf[2 * p][0], Bf[2 * p][1], Bf[2 * p + 1][0], Bf[2 * p + 1][1],
                        buf + boff + p * 2304 + kb);
#pragma unroll
            for (int mt = 0; mt < 4; mt++)
#pragma unroll
                for (int nt = 0; nt < 4; nt++)
                    MMA_F16(acc[mt][nt][0], acc[mt][nt][1], acc[mt][nt][2], acc[mt][nt][3],
                            Af[mt][0], Af[mt][1], Af[mt][2], Af[mt][3],
                            Bf[nt][0], Bf[nt][1]);
        }
    }

#pragma unroll
    for (int mt = 0; mt < 4; mt++) {
        int r = wr * 64 + mt * 16 + g;
#pragma unroll
        for (int nt = 0; nt < 4; nt++) {
            int col = wc * 32 + nt * 8 + 2 * tg;
            __half2 h0 = __floats2half2_rn(acc[mt][nt][0], acc[mt][nt][1]);
            __half2 h1 = __floats2half2_rn(acc[mt][nt][2], acc[mt][nt][3]);
            *(__half2*)(C + (size_t)r * NN + col)       = h0;
            *(__half2*)(C + (size_t)(r + 8) * NN + col) = h1;
        }
    }
#undef EIN_ISSUE
}

// ---- K4: out = (g * gather(o)) @ W_o^T via fp16 MMA ----
__global__ void __launch_bounds__(256) k_out_h(const float* __restrict__ Wo,
                                               float* __restrict__ out) {
    extern __shared__ __half sh[];
    __half* prodA = sh;               // [64][264]
    __half* WoS   = sh + 64 * 264;    // [64][264]
    int t = threadIdx.x, lane = t & 31, wid = t >> 5;
    int g = lane >> 2, tg = lane & 3;
    int rr = lane & 7, qd = lane >> 3;
    int wm = wid & 1, wn = wid >> 1;
    int rowBase = blockIdx.x * 64;

#pragma unroll
    for (int q = 0; q < 16; q++) {
        int idx = q * 256 + t;
        int cm = idx >> 6, kf = idx & 63;
        float4 f = *(const float4*)(Wo + (size_t)cm * HC + kf * 4);
        __half2 h0 = __floats2half2_rn(f.x, f.y);
        __half2 h1 = __floats2half2_rn(f.z, f.w);
        *(uint2*)&WoS[cm * 264 + kf * 4] = make_uint2(*(unsigned*)&h0, *(unsigned*)&h1);
    }
    {
        int hh = t >> 5, c = t & 31;
#pragma unroll 8
        for (int q = 0; q < 64; q++) {
            int gr = rowBase + q;
            int s = gr >> 9, i = gr & 511;
            float gv = __half2float(d_gh[(size_t)gr * HC + t]);
            float ov = __half2float(d_oh[((size_t)hh * I_ + i) * NN + s * CH + c]);
            prodA[q * 264 + t] = __float2half(gv * ov);
        }
    }
    __syncthreads();

    uint32_t smBase = smem_u32(sh);
    uint32_t aoff = ((wm * 32 + rr + ((qd & 1) << 3)) * 264 + ((qd >> 1) << 3)) * 2;
    uint32_t boff = (64 * 264 + (wn * 16 + rr + ((qd >> 1) << 3)) * 264 + ((qd & 1) << 3)) * 2;

    float acc[2][2][4];
#pragma unroll
    for (int a = 0; a < 2; a++)
#pragma unroll
        for (int b = 0; b < 2; b++)
#pragma unroll
            for (int c = 0; c < 4; c++) acc[a][b][c] = 0.f;

#pragma unroll
    for (int ks = 0; ks < 16; ks++) {
        uint32_t kb = ks * 32;
        uint32_t Af[2][4], Bf[2][2];
#pragma unroll
        for (int mt = 0; mt < 2; mt++)
            ldsm_x4(Af[mt][0], Af[mt][1], Af[mt][2], Af[mt][3],
                    smBase + aoff + mt * (16 * 264 * 2) + kb);
        ldsm_x4(Bf[0][0], Bf[0][1], Bf[1][0], Bf[1][1], smBase + boff + kb);
#pragma unroll
        for (int mt = 0; mt < 2; mt++)
#pragma unroll
            for (int nt = 0; nt < 2; nt++)
                MMA_F16(acc[mt][nt][0], acc[mt][nt][1], acc[mt][nt][2], acc[mt][nt][3],
                        Af[mt][0], Af[mt][1], Af[mt][2], Af[mt][3],
                        Bf[nt][0], Bf[nt][1]);
    }

#pragma unroll
    for (int mt = 0; mt < 2; mt++) {
        int r0 = rowBase + wm * 32 + mt * 16 + g;
#pragma unroll
        for (int nt = 0; nt < 2; nt++) {
            int col = wn * 16 + nt * 8 + 2 * tg;
            *(float2*)(out + (size_t)r0 * CM + col) =
                make_float2(acc[mt][nt][0], acc[mt][nt][1]);
            *(float2*)(out + (size_t)(r0 + 8) * CM + col) =
                make_float2(acc[mt][nt][2], acc[mt][nt][3]);
        }
    }
}

extern "C" void kernel_launch(void* const* d_in, const int* in_sizes, int n_in,
                              void* d_out, int out_size) {
    const float* m        = (const float*)d_in[0];
    const float* z        = (const float*)d_in[1];
    const float* msa_mask = (const float*)d_in[2];
    const float* z_mask   = (const float*)d_in[3];
    const float* ln_m_g   = (const float*)d_in[4];
    const float* ln_m_b   = (const float*)d_in[5];
    const float* W_v      = (const float*)d_in[6];
    const float* W_g      = (const float*)d_in[7];
    const float* ln_z_g   = (const float*)d_in[8];
    const float* ln_z_b   = (const float*)d_in[9];
    const float* W_b      = (const float*)d_in[10];
    const float* W_o      = (const float*)d_in[11];
    float* out = (float*)d_out;

    const int SMEM_VG  = 2 * 128 * 72 * 2;            // 36864
    const int SMEM_EIN = 3 * 256 * 72 * 2;            // 110592
    const int SMEM_OUT = 2 * 64 * 264 * 2;            // 67584
    cudaFuncSetAttribute(k_vg_h,    cudaFuncAttributeMaxDynamicSharedMemorySize, SMEM_VG);
    cudaFuncSetAttribute(k_einsum_h,cudaFuncAttributeMaxDynamicSharedMemorySize, SMEM_EIN);
    cudaFuncSetAttribute(k_out_h,   cudaFuncAttributeMaxDynamicSharedMemorySize, SMEM_OUT);

    // 4 launches: stitched bsm+ln (0), vg (1), einsum (2), out (3 = profiled)
    k_bsm_ln<<<I_ + S_ * I_ / 8, 256>>>(z, ln_z_g, ln_z_b, W_b, z_mask,
                                        m, ln_m_g, ln_m_b);          // 0
    k_vg_h<<<dim3(4, 1024), 256, SMEM_VG>>>(W_v, W_g, msa_mask);     // 1
    k_einsum_h<<<dim3(4, 64, 8), 256, SMEM_EIN>>>();                 // 2
    k_out_h<<<S_ * I_ / 64, 256, SMEM_OUT>>>(W_o, out);              // 3 (profiled)
}

// round 15
// speedup vs baseline: 1.0964x; 1.0143x over previous
#include <cuda_runtime.h>
#include <cuda_fp16.h>
#include <math.h>
#include <cstdint>

#define S_  256
#define I_  512
#define CM  64
#define CZ  128
#define H_  8
#define CH  32
#define HC  256
#define NN  (S_*CH)   // 8192
#define EPS 1e-5f

// ---- scratch ----
__device__ __half d_mh[(size_t)S_*I_*CM];     // LN(m) fp16
__device__ __half d_vh[(size_t)H_*NN*I_];     // v fp16 [h][n][j], n = s*32+c
__device__ __half d_gh[(size_t)S_*I_*HC];     // sigmoid(g) fp16 [s*i][hc]
__device__ __half d_wh[(size_t)H_*I_*I_];     // softmax(w) fp16 [h][i][j]
__device__ __half d_oh[(size_t)H_*I_*NN];     // o fp16 [h][i][n]

__device__ __forceinline__ float warp_sum(float v) {
#pragma unroll
    for (int o = 16; o; o >>= 1) v += __shfl_xor_sync(0xffffffffu, v, o);
    return v;
}
__device__ __forceinline__ float warp_max(float v) {
#pragma unroll
    for (int o = 16; o; o >>= 1) v = fmaxf(v, __shfl_xor_sync(0xffffffffu, v, o));
    return v;
}
__device__ __forceinline__ uint32_t smem_u32(const void* p) {
    uint32_t a;
    asm("{ .reg .u64 t; cvta.to.shared.u64 t, %1; cvt.u32.u64 %0, t; }" : "=r"(a) : "l"(p));
    return a;
}
__device__ __forceinline__ void ldsm_x4(uint32_t& r0, uint32_t& r1, uint32_t& r2,
                                        uint32_t& r3, uint32_t addr) {
    asm volatile("ldmatrix.sync.aligned.m8n8.x4.shared.b16 {%0,%1,%2,%3}, [%4];"
                 : "=r"(r0), "=r"(r1), "=r"(r2), "=r"(r3) : "r"(addr));
}
__device__ __forceinline__ void cpa16(uint32_t dst, const void* src) {
    asm volatile("cp.async.cg.shared.global [%0], [%1], 16;" :: "r"(dst), "l"(src));
}
#define CP_COMMIT() asm volatile("cp.async.commit_group;" ::: "memory")

#define MMA_F16(d0,d1,d2,d3,a0,a1,a2,a3,b0,b1) \
    asm volatile("mma.sync.aligned.m16n8k16.row.col.f32.f16.f16.f32 " \
                 "{%0,%1,%2,%3},{%4,%5,%6,%7},{%8,%9},{%0,%1,%2,%3};" \
                 : "+f"(d0),"+f"(d1),"+f"(d2),"+f"(d3) \
                 : "r"(a0),"r"(a1),"r"(a2),"r"(a3),"r"(b0),"r"(b1))

// ---- K1: STITCHED — blocks [0,512): b-projection+softmax; blocks [512,...): LN(m) ----
__global__ void __launch_bounds__(256) k_bsm_ln(const float* __restrict__ z,
                                                const float* __restrict__ zg,
                                                const float* __restrict__ zb,
                                                const float* __restrict__ Wb,
                                                const float* __restrict__ zmask,
                                                const float* __restrict__ m,
                                                const float* __restrict__ lng,
                                                const float* __restrict__ lnb) {
    __shared__ __align__(16) float Wbs[H_ * CZ];
    __shared__ __align__(16) float zgs[CZ], zbs[CZ];
    __shared__ __align__(16) float bs[8][516];
    int t = threadIdx.x;
    int lane = t & 31, wid = t >> 5;

    if (blockIdx.x >= I_) {
        int row  = (blockIdx.x - I_) * 8 + wid;
        const float2 v = *(const float2*)(m + (size_t)row * CM + lane * 2);
        float s  = warp_sum(v.x + v.y);
        float mu = s * (1.f / 64.f);
        float d0 = v.x - mu, d1 = v.y - mu;
        float var = warp_sum(d0 * d0 + d1 * d1) * (1.f / 64.f);
        float rs = rsqrtf(var + EPS);
        float2 gg = *(const float2*)(lng + lane * 2);
        float2 bb = *(const float2*)(lnb + lane * 2);
        __half2 o = __floats2half2_rn(d0 * rs * gg.x + bb.x, d1 * rs * gg.y + bb.y);
        *(__half2*)(d_mh + (size_t)row * CM + lane * 2) = o;
        return;
    }

    int grp = t >> 3, sub = t & 7;
    int i = blockIdx.x;
    for (int idx = t; idx < H_ * CZ; idx += 256) Wbs[idx] = Wb[idx];
    if (t < CZ) { zgs[t] = zg[t]; zbs[t] = zb[t]; }
    __syncthreads();

#pragma unroll 1
    for (int p = 0; p < 16; p++) {
        int j = p * 32 + grp;
        const float* zp = z + ((size_t)i * I_ + j) * CZ + sub * 16;
        float4 v[4];
#pragma unroll
        for (int q = 0; q < 4; q++) v[q] = *(const float4*)(zp + q * 4);
        float s = 0.f, ss = 0.f;
#pragma unroll
        for (int q = 0; q < 4; q++) {
            s  += v[q].x + v[q].y + v[q].z + v[q].w;
            ss += v[q].x * v[q].x + v[q].y * v[q].y + v[q].z * v[q].z + v[q].w * v[q].w;
        }
#pragma unroll
        for (int o = 4; o; o >>= 1) {
            s  += __shfl_xor_sync(0xffffffffu, s, o);
            ss += __shfl_xor_sync(0xffffffffu, ss, o);
        }
        float mu = s * (1.f / 128.f);
        float var = ss * (1.f / 128.f) - mu * mu;
        float rs = rsqrtf(var + EPS);

        float xn[16];
#pragma unroll
        for (int q = 0; q < 4; q++) {
            float4 g4 = *(const float4*)(zgs + sub * 16 + q * 4);
            float4 b4 = *(const float4*)(zbs + sub * 16 + q * 4);
            xn[q * 4 + 0] = (v[q].x - mu) * rs * g4.x + b4.x;
            xn[q * 4 + 1] = (v[q].y - mu) * rs * g4.y + b4.y;
            xn[q * 4 + 2] = (v[q].z - mu) * rs * g4.z + b4.z;
            xn[q * 4 + 3] = (v[q].w - mu) * rs * g4.w + b4.w;
        }
        float pv[8];
#pragma unroll
        for (int h = 0; h < 8; h++) {
            float a = 0.f;
#pragma unroll
            for (int q = 0; q < 4; q++) {
                float4 w4 = *(const float4*)(Wbs + h * CZ + sub * 16 + q * 4);
                a += xn[q * 4 + 0] * w4.x + xn[q * 4 + 1] * w4.y +
                     xn[q * 4 + 2] * w4.z + xn[q * 4 + 3] * w4.w;
            }
            pv[h] = a;
        }
        bool b4_ = sub & 4, b2_ = sub & 2, b1_ = sub & 1;
        float q4[4];
#pragma unroll
        for (int h = 0; h < 4; h++) {
            float send = b4_ ? pv[h] : pv[h + 4];
            float recv = __shfl_xor_sync(0xffffffffu, send, 4);
            q4[h] = (b4_ ? pv[h + 4] : pv[h]) + recv;
        }
        float r2[2];
#pragma unroll
        for (int h = 0; h < 2; h++) {
            float send = b2_ ? q4[h] : q4[h + 2];
            float recv = __shfl_xor_sync(0xffffffffu, send, 2);
            r2[h] = (b2_ ? q4[h + 2] : q4[h]) + recv;
        }
        float send = b1_ ? r2[0] : r2[1];
        float recv = __shfl_xor_sync(0xffffffffu, send, 1);
        float val = (b1_ ? r2[1] : r2[0]) + recv;
        float mval = zmask[(size_t)i * I_ + j];
        bs[sub][j] = val + 1e8f * (mval - 1.f);
    }
    __syncthreads();

    {
        int h = wid;
        float4 x[4];
#pragma unroll
        for (int q = 0; q < 4; q++) x[q] = *(const float4*)&bs[h][q * 128 + lane * 4];
        float mx = -3.4e38f;
#pragma unroll
        for (int q = 0; q < 4; q++)
            mx = fmaxf(mx, fmaxf(fmaxf(x[q].x, x[q].y), fmaxf(x[q].z, x[q].w)));
        mx = warp_max(mx);
        float sum = 0.f;
#pragma unroll
        for (int q = 0; q < 4; q++) {
            x[q].x = __expf(x[q].x - mx); x[q].y = __expf(x[q].y - mx);
            x[q].z = __expf(x[q].z - mx); x[q].w = __expf(x[q].w - mx);
            sum += x[q].x + x[q].y + x[q].z + x[q].w;
        }
        sum = warp_sum(sum);
        float inv = 1.f / sum;
        __half* wp = d_wh + ((size_t)h * I_ + i) * I_;
#pragma unroll
        for (int q = 0; q < 4; q++) {
            __half2 h01 = __floats2half2_rn(x[q].x * inv, x[q].y * inv);
            __half2 h23 = __floats2half2_rn(x[q].z * inv, x[q].w * inv);
            *(uint2*)(wp + q * 128 + lane * 4) =
                make_uint2(*(unsigned*)&h01, *(unsigned*)&h23);
        }
    }
}

// ------- K2: fused v+g projection, fp16 MMA + ldmatrix; direct scatter epilogues -------
__global__ void __launch_bounds__(256, 2) k_vg_h(const float* __restrict__ Wv,
                                                 const float* __restrict__ Wg,
                                                 const float* __restrict__ msk) {
    extern __shared__ __half svh[];           // As[128][72] | Ws[128][72]
    const uint32_t WS_OFF = 128 * 72;
    int t = threadIdx.x;
    int lane = t & 31, warp = t >> 5;
    int g = lane >> 2, tg = lane & 3;
    int wr = warp >> 2, wc = warp & 3;
    int rr = lane & 7, qd = lane >> 3;
    int mBase = blockIdx.y * 128, nBase = blockIdx.x * 128;
    bool isV = (blockIdx.x < 2);

#pragma unroll
    for (int q = 0; q < 4; q++) {
        int idx = q * 256 + t;
        int row = idx >> 3, u8 = idx & 7;
        uint4 v4 = *(const uint4*)(d_mh + (size_t)(mBase + row) * CM + u8 * 8);
        *(uint4*)&svh[row * 72 + u8 * 8] = v4;
    }
#pragma unroll
    for (int q = 0; q < 4; q++) {
        int idx = q * 256 + t;
        int col = idx >> 3, u8 = idx & 7;
        int gc = nBase + col;
        const float* Wp = (gc < 256) ? (Wv + (size_t)gc * CM)
                                     : (Wg + (size_t)(gc - 256) * CM);
        float4 f0 = *(const float4*)(Wp + u8 * 8);
        float4 f1 = *(const float4*)(Wp + u8 * 8 + 4);
        __half2 h0 = __floats2half2_rn(f0.x, f0.y);
        __half2 h1 = __floats2half2_rn(f0.z, f0.w);
        __half2 h2 = __floats2half2_rn(f1.x, f1.y);
        __half2 h3 = __floats2half2_rn(f1.z, f1.w);
        uint4 pk;
        pk.x = *(unsigned*)&h0; pk.y = *(unsigned*)&h1;
        pk.z = *(unsigned*)&h2; pk.w = *(unsigned*)&h3;
        *(uint4*)&svh[WS_OFF + col * 72 + u8 * 8] = pk;
    }
    __syncthreads();

    uint32_t smBase = smem_u32(svh);
    uint32_t aoff = ((wr * 64 + rr + ((qd & 1) << 3)) * 72 + ((qd >> 1) << 3)) * 2;
    uint32_t boff = WS_OFF * 2 + ((wc * 32 + rr + ((qd >> 1) << 3)) * 72 + ((qd & 1) << 3)) * 2;

    float acc[4][4][4];
#pragma unroll
    for (int a = 0; a < 4; a++)
#pragma unroll
        for (int b = 0; b < 4; b++)
#pragma unroll
            for (int c = 0; c < 4; c++) acc[a][b][c] = 0.f;

#pragma unroll
    for (int ks = 0; ks < 4; ks++) {
        uint32_t kb = ks * 32;
        uint32_t Af[4][4], Bf[4][2];
#pragma unroll
        for (int mt = 0; mt < 4; mt++)
            ldsm_x4(Af[mt][0], Af[mt][1], Af[mt][2], Af[mt][3],
                    smBase + aoff + mt * 2304 + kb);
#pragma unroll
        for (int p = 0; p < 2; p++)
            ldsm_x4(Bf[2 * p][0], Bf[2 * p][1], Bf[2 * p + 1][0], Bf[2 * p + 1][1],
                    smBase + boff + p * 2304 + kb);
#pragma unroll
        for (int mt = 0; mt < 4; mt++)
#pragma unroll
            for (int nt = 0; nt < 4; nt++)
                MMA_F16(acc[mt][nt][0], acc[mt][nt][1], acc[mt][nt][2], acc[mt][nt][3],
                        Af[mt][0], Af[mt][1], Af[mt][2], Af[mt][3],
                        Bf[nt][0], Bf[nt][1]);
    }

    if (isV) {
#pragma unroll
        for (int mt = 0; mt < 4; mt++) {
            int R0 = mBase + wr * 64 + mt * 16 + g;
            int R1 = R0 + 8;
            float mk0 = msk[R0], mk1 = msk[R1];
#pragma unroll
            for (int nt = 0; nt < 4; nt++) {
                int Cc = nBase + wc * 32 + nt * 8 + 2 * tg;
                int hh = Cc >> 5, c = Cc & 31;
                int s = R0 >> 9, j = R0 & 511;
                __half* vp = d_vh + ((size_t)hh * NN + (size_t)s * CH + c) * I_ + j;
                vp[0]       = __float2half(acc[mt][nt][0] * mk0);
                vp[I_]      = __float2half(acc[mt][nt][1] * mk0);
                vp[8]       = __float2half(acc[mt][nt][2] * mk1);
                vp[I_ + 8]  = __float2half(acc[mt][nt][3] * mk1);
            }
        }
    } else {
#pragma unroll
        for (int mt = 0; mt < 4; mt++) {
            int R0 = mBase + wr * 64 + mt * 16 + g;
            int R1 = R0 + 8;
#pragma unroll
            for (int nt = 0; nt < 4; nt++) {
                int cg = (nBase - 256) + wc * 32 + nt * 8 + 2 * tg;
                __half2 o0 = __floats2half2_rn(1.f / (1.f + __expf(-acc[mt][nt][0])),
                                               1.f / (1.f + __expf(-acc[mt][nt][1])));
                __half2 o1 = __floats2half2_rn(1.f / (1.f + __expf(-acc[mt][nt][2])),
                                               1.f / (1.f + __expf(-acc[mt][nt][3])));
                *(__half2*)(d_gh + (size_t)R0 * HC + cg) = o0;
                *(__half2*)(d_gh + (size_t)R1 * HC + cg) = o1;
            }
        }
    }
}

// ---- K3: einsum fp16 MMA; 128x128 tile, BK=64, cp.async 3-stage, 2 CTAs/SM ----
__global__ void __launch_bounds__(256, 2) k_einsum_h() {
    extern __shared__ __half smh[];
    const uint32_t BUFB = 256 * 72 * 2;
    int t = threadIdx.x, lane = t & 31, wid = t >> 5;
    int g = lane >> 2, tg = lane & 3;
    int wr = wid & 1, wc = wid >> 1;
    int rr = lane & 7, qd = lane >> 3;
    int h = blockIdx.z;
    int mBase = blockIdx.x * 128, nBase = blockIdx.y * 128;
    const __half* Ag = d_wh + ((size_t)h * I_ + mBase) * I_;
    const __half* Bg = d_vh + ((size_t)h * NN + nBase) * I_;
    __half*       C  = d_oh + ((size_t)h * I_ + mBase) * NN + nBase;

    uint32_t smBase = smem_u32(smh);
    int crow = t >> 2, cc4 = t & 3;
    const __half* srcA0 = Ag + (size_t)crow * I_;
    const __half* srcA1 = srcA0 + (size_t)64 * I_;
    const __half* srcB0 = Bg + (size_t)crow * I_;
    const __half* srcB1 = srcB0 + (size_t)64 * I_;
    uint32_t dA0a = (crow * 72 + cc4 * 8) * 2;
    uint32_t dA0b = (crow * 72 + (cc4 + 4) * 8) * 2;
    uint32_t dA1a = dA0a + 64 * 72 * 2;
    uint32_t dA1b = dA0b + 64 * 72 * 2;
    uint32_t BOFF = 128 * 72 * 2;

    uint32_t aoff = ((wr * 64 + rr + ((qd & 1) << 3)) * 72 + ((qd >> 1) << 3)) * 2;
    uint32_t boff = BOFF + ((wc * 32 + rr + ((qd >> 1) << 3)) * 72 + ((qd & 1) << 3)) * 2;

#define EIN_ISSUE(kc) do {                                               \
        uint32_t _b = smBase + ((kc) % 3) * BUFB;                        \
        int _k = (kc) * 64;                                              \
        cpa16(_b + dA0a,        srcA0 + _k + cc4 * 8);                   \
        cpa16(_b + dA0b,        srcA0 + _k + (cc4 + 4) * 8);             \
        cpa16(_b + dA1a,        srcA1 + _k + cc4 * 8);                   \
        cpa16(_b + dA1b,        srcA1 + _k + (cc4 + 4) * 8);             \
        cpa16(_b + BOFF + dA0a, srcB0 + _k + cc4 * 8);                   \
        cpa16(_b + BOFF + dA0b, srcB0 + _k + (cc4 + 4) * 8);             \
        cpa16(_b + BOFF + dA1a, srcB1 + _k + cc4 * 8);                   \
        cpa16(_b + BOFF + dA1b, srcB1 + _k + (cc4 + 4) * 8);             \
        CP_COMMIT();                                                     \
    } while (0)

    EIN_ISSUE(0);
    EIN_ISSUE(1);

    float acc[4][4][4];
#pragma unroll
    for (int a = 0; a < 4; a++)
#pragma unroll
        for (int b = 0; b < 4; b++)
#pragma unroll
            for (int c = 0; c < 4; c++) acc[a][b][c] = 0.f;

#pragma unroll 1
    for (int kc = 0; kc < 8; kc++) {
        if (kc < 7) asm volatile("cp.async.wait_group 1;" ::: "memory");
        else        asm volatile("cp.async.wait_group 0;" ::: "memory");
        __syncthreads();
        if (kc < 6) EIN_ISSUE(kc + 2);
        uint32_t buf = smBase + (kc % 3) * BUFB;
#pragma unroll
        for (int ks = 0; ks < 4; ks++) {
            uint32_t kb = ks * 32;
            uint32_t Af[4][4], Bf[4][2];
#pragma unroll
            for (int mt = 0; mt < 4; mt++)
                ldsm_x4(Af[mt][0], Af[mt][1], Af[mt][2], Af[mt][3],
                        buf + aoff + mt * 2304 + kb);
#pragma unroll
            for (int p = 0; p < 2; p++)
                ldsm_x4(Bf[2 * p][0], Bf[2 * p][1], Bf[2 * p + 1][0], Bf[2 * p + 1][1],
                        buf + boff + p * 2304 + kb);
#pragma unroll
            for (int mt = 0; mt < 4; mt++)
#pragma unroll
                for (int nt = 0; nt < 4; nt++)
                    MMA_F16(acc[mt][nt][0], acc[mt][nt][1], acc[mt][nt][2], acc[mt][nt][3],
                            Af[mt][0], Af[mt][1], Af[mt][2], Af[mt][3],
                            Bf[nt][0], Bf[nt][1]);
        }
    }

#pragma unroll
    for (int mt = 0; mt < 4; mt++) {
        int r = wr * 64 + mt * 16 + g;
#pragma unroll
        for (int nt = 0; nt < 4; nt++) {
            int col = wc * 32 + nt * 8 + 2 * tg;
            __half2 h0 = __floats2half2_rn(acc[mt][nt][0], acc[mt][nt][1]);
            __half2 h1 = __floats2half2_rn(acc[mt][nt][2], acc[mt][nt][3]);
            *(__half2*)(C + (size_t)r * NN + col)       = h0;
            *(__half2*)(C + (size_t)(r + 8) * NN + col) = h1;
        }
    }
#undef EIN_ISSUE
}

// ---- K4: out = (g * gather(o)) @ W_o^T via fp16 MMA; vectorized gather ----
__global__ void __launch_bounds__(256) k_out_h(const float* __restrict__ Wo,
                                               float* __restrict__ out) {
    extern __shared__ __half sh[];
    __half* prodA = sh;               // [64][264]
    __half* WoS   = sh + 64 * 264;    // [64][264]
    int t = threadIdx.x, lane = t & 31, wid = t >> 5;
    int g = lane >> 2, tg = lane & 3;
    int rr = lane & 7, qd = lane >> 3;
    int wm = wid & 1, wn = wid >> 1;
    int rowBase = blockIdx.x * 64;

#pragma unroll
    for (int q = 0; q < 16; q++) {
        int idx = q * 256 + t;
        int cm = idx >> 6, kf = idx & 63;
        float4 f = *(const float4*)(Wo + (size_t)cm * HC + kf * 4);
        __half2 h0 = __floats2half2_rn(f.x, f.y);
        __half2 h1 = __floats2half2_rn(f.z, f.w);
        *(uint2*)&WoS[cm * 264 + kf * 4] = make_uint2(*(unsigned*)&h0, *(unsigned*)&h1);
    }
    // vectorized gather: thread owns one 8-half chunk (kk = chunk*8)
    {
        int chunk = t & 31;            // 32 chunks cover HC=256
        int rsub  = t >> 5;            // 8 rows per pass
        int hh = chunk >> 2;
        int c  = (chunk & 3) * 8;
        const __half* ghp = d_gh + (size_t)(rowBase + rsub) * HC + chunk * 8;
        __half* dst = prodA + rsub * 264 + chunk * 8;
#pragma unroll
        for (int q = 0; q < 8; q++) {
            int gr = rowBase + q * 8 + rsub;
            int s = gr >> 9, i = gr & 511;
            uint4 gv4 = *(const uint4*)(ghp + (size_t)(q * 8) * HC);
            uint4 ov4 = *(const uint4*)(d_oh + ((size_t)hh * I_ + i) * NN + s * CH + c);
            uint4 pk;
            ((__half2*)&pk)[0] = __hmul2(((__half2*)&gv4)[0], ((__half2*)&ov4)[0]);
            ((__half2*)&pk)[1] = __hmul2(((__half2*)&gv4)[1], ((__half2*)&ov4)[1]);
            ((__half2*)&pk)[2] = __hmul2(((__half2*)&gv4)[2], ((__half2*)&ov4)[2]);
            ((__half2*)&pk)[3] = __hmul2(((__half2*)&gv4)[3], ((__half2*)&ov4)[3]);
            *(uint4*)(dst + q * 8 * 264) = pk;
        }
    }
    __syncthreads();

    uint32_t smBase = smem_u32(sh);
    uint32_t aoff = ((wm * 32 + rr + ((qd & 1) << 3)) * 264 + ((qd >> 1) << 3)) * 2;
    uint32_t boff = (64 * 264 + (wn * 16 + rr + ((qd >> 1) << 3)) * 264 + ((qd & 1) << 3)) * 2;

    float acc[2][2][4];
#pragma unroll
    for (int a = 0; a < 2; a++)
#pragma unroll
        for (int b = 0; b < 2; b++)
#pragma unroll
            for (int c = 0; c < 4; c++) acc[a][b][c] = 0.f;

#pragma unroll
    for (int ks = 0; ks < 16; ks++) {
        uint32_t kb = ks * 32;
        uint32_t Af[2][4], Bf[2][2];
#pragma unroll
        for (int mt = 0; mt < 2; mt++)
            ldsm_x4(Af[mt][0], Af[mt][1], Af[mt][2], Af[mt][3],
                    smBase + aoff + mt * (16 * 264 * 2) + kb);
        ldsm_x4(Bf[0][0], Bf[0][1], Bf[1][0], Bf[1][1], smBase + boff + kb);
#pragma unroll
        for (int mt = 0; mt < 2; mt++)
#pragma unroll
            for (int nt = 0; nt < 2; nt++)
                MMA_F16(acc[mt][nt][0], acc[mt][nt][1], acc[mt][nt][2], acc[mt][nt][3],
                        Af[mt][0], Af[mt][1], Af[mt][2], Af[mt][3],
                        Bf[nt][0], Bf[nt][1]);
    }

#pragma unroll
    for (int mt = 0; mt < 2; mt++) {
        int r0 = rowBase + wm * 32 + mt * 16 + g;
#pragma unroll
        for (int nt = 0; nt < 2; nt++) {
            int col = wn * 16 + nt * 8 + 2 * tg;
            *(float2*)(out + (size_t)r0 * CM + col) =
                make_float2(acc[mt][nt][0], acc[mt][nt][1]);
            *(float2*)(out + (size_t)(r0 + 8) * CM + col) =
                make_float2(acc[mt][nt][2], acc[mt][nt][3]);
        }
    }
}

extern "C" void kernel_launch(void* const* d_in, const int* in_sizes, int n_in,
                              void* d_out, int out_size) {
    const float* m        = (const float*)d_in[0];
    const float* z        = (const float*)d_in[1];
    const float* msa_mask = (const float*)d_in[2];
    const float* z_mask   = (const float*)d_in[3];
    const float* ln_m_g   = (const float*)d_in[4];
    const float* ln_m_b   = (const float*)d_in[5];
    const float* W_v      = (const float*)d_in[6];
    const float* W_g      = (const float*)d_in[7];
    const float* ln_z_g   = (const float*)d_in[8];
    const float* ln_z_b   = (const float*)d_in[9];
    const float* W_b      = (const float*)d_in[10];
    const float* W_o      = (const float*)d_in[11];
    float* out = (float*)d_out;

    const int SMEM_VG  = 2 * 128 * 72 * 2;            // 36864
    const int SMEM_EIN = 3 * 256 * 72 * 2;            // 110592
    const int SMEM_OUT = 2 * 64 * 264 * 2;            // 67584
    cudaFuncSetAttribute(k_vg_h,    cudaFuncAttributeMaxDynamicSharedMemorySize, SMEM_VG);
    cudaFuncSetAttribute(k_einsum_h,cudaFuncAttributeMaxDynamicSharedMemorySize, SMEM_EIN);
    cudaFuncSetAttribute(k_out_h,   cudaFuncAttributeMaxDynamicSharedMemorySize, SMEM_OUT);

    k_bsm_ln<<<I_ + S_ * I_ / 8, 256>>>(z, ln_z_g, ln_z_b, W_b, z_mask,
                                        m, ln_m_g, ln_m_b);          // 0
    k_vg_h<<<dim3(4, 1024), 256, SMEM_VG>>>(W_v, W_g, msa_mask);     // 1
    k_einsum_h<<<dim3(4, 64, 8), 256, SMEM_EIN>>>();                 // 2
    k_out_h<<<S_ * I_ / 64, 256, SMEM_OUT>>>(W_o, out);              // 3 (profiled)
}